// round 3
// baseline (speedup 1.0000x reference)
#include <cuda_runtime.h>

#define SENS 61
#define HID  64
#define NSTEPS 10
#define TPB  128

typedef unsigned long long u64;

// Dormand–Prince 5(4) tableau
__constant__ float c_A[6][5] = {
  {0.f, 0.f, 0.f, 0.f, 0.f},
  {(float)(1.0/5.0), 0.f, 0.f, 0.f, 0.f},
  {(float)(3.0/40.0), (float)(9.0/40.0), 0.f, 0.f, 0.f},
  {(float)(44.0/45.0), (float)(-56.0/15.0), (float)(32.0/9.0), 0.f, 0.f},
  {(float)(19372.0/6561.0), (float)(-25360.0/2187.0), (float)(64448.0/6561.0), (float)(-212.0/729.0), 0.f},
  {(float)(9017.0/3168.0), (float)(-355.0/33.0), (float)(46732.0/5247.0), (float)(49.0/176.0), (float)(-5103.0/18656.0)}
};
__constant__ float c_C[6] = {0.f, 0.2f, 0.3f, 0.8f, (float)(8.0/9.0), 1.f};
__constant__ float c_B[6] = {(float)(35.0/384.0), 0.f, (float)(500.0/1113.0),
                             (float)(125.0/192.0), (float)(-2187.0/6784.0), (float)(11.0/84.0)};

// ---- packed f32x2 + fast tanh helpers ----
__device__ __forceinline__ float ftanh(float x) {
  float r; asm("tanh.approx.f32 %0, %1;" : "=f"(r) : "f"(x)); return r;
}
__device__ __forceinline__ u64 pk2(float lo, float hi) {
  u64 r; asm("mov.b64 %0, {%1, %2};" : "=l"(r) : "f"(lo), "f"(hi)); return r;
}
__device__ __forceinline__ void upk2(u64 v, float& lo, float& hi) {
  asm("mov.b64 {%0, %1}, %2;" : "=f"(lo), "=f"(hi) : "l"(v));
}
__device__ __forceinline__ u64 fma2(u64 a, u64 b, u64 c) {
  u64 d; asm("fma.rn.f32x2 %0, %1, %2, %3;" : "=l"(d) : "l"(a), "l"(b), "l"(c)); return d;
}
__device__ __forceinline__ u64 mul2(u64 a, u64 b) {
  u64 d; asm("mul.rn.f32x2 %0, %1, %2;" : "=l"(d) : "l"(a), "l"(b)); return d;
}

// Shared layout (floats):
//   sW1y : [64][4]   rows {W1[0],W1[1],W1[2],W1[64]} transposed (y + t weights)
//   sW2  : [64][64]
//   sW3T : [3][64]   transposed W3 (+1 pad col)
//   sB2  : [64]
//   sB3  : [4]
//   sS1  : [64][TPB] per-thread sensory contribution incl. b1
#define OFF_W1Y 0
#define OFF_W2  (OFF_W1Y + HID*4)
#define OFF_W3T (OFF_W2 + HID*HID)
#define OFF_B2  (OFF_W3T + 4*HID)
#define OFF_B3  (OFF_B2 + HID)
#define OFF_S1  (OFF_B3 + 4)
#define SMEM_FLOATS (OFF_S1 + HID*TPB)

__global__ void __launch_bounds__(TPB, 3)
ode_kernel(const float* __restrict__ pad0, const float* __restrict__ sens,
           const float* __restrict__ W1, const float* __restrict__ b1,
           const float* __restrict__ W2, const float* __restrict__ b2,
           const float* __restrict__ W3, const float* __restrict__ b3,
           const float* __restrict__ scale, float* __restrict__ out, int nrows)
{
  extern __shared__ float sm[];
  float* sW1y = sm + OFF_W1Y;
  float* sW2  = sm + OFF_W2;
  float* sW3T = sm + OFF_W3T;
  float* sB2  = sm + OFF_B2;
  float* sB3  = sm + OFF_B3;
  float* sS1  = sm + OFF_S1;

  const int tid = threadIdx.x;

  // ---- cooperative weight staging ----
  for (int j = tid; j < HID; j += TPB) {
    sW1y[j*4 + 0] = W1[0*HID + j];
    sW1y[j*4 + 1] = W1[1*HID + j];
    sW1y[j*4 + 2] = W1[2*HID + j];
    sW1y[j*4 + 3] = W1[64*HID + j];   // time row
  }
  for (int idx = tid; idx < HID*HID; idx += TPB) sW2[idx] = W2[idx];
  for (int j = tid; j < HID; j += TPB) {
    sW3T[0*HID + j] = W3[j*3 + 0];
    sW3T[1*HID + j] = W3[j*3 + 1];
    sW3T[2*HID + j] = W3[j*3 + 2];
    sB2[j] = b2[j];
  }
  if (tid < 4) sB3[tid] = (tid < 3) ? b3[tid] : 0.0f;
  __syncthreads();

  const int row = blockIdx.x * TPB + tid;
  if (row >= nrows) return;

  // ---- prologue: s1[j] = b1[j] + sensory . W1[3:64, j]  (constant over 60 evals) ----
  {
    const float* srow = sens + (size_t)row * SENS;
    #pragma unroll
    for (int half = 0; half < 2; half++) {       // 2 passes of 8 float4 to bound live regs
      float4 acc[8];
      const float4* b1v = (const float4*)b1;
      #pragma unroll
      for (int g = 0; g < 8; g++) acc[g] = __ldg(b1v + half*8 + g);
      for (int s2 = 0; s2 < SENS; s2++) {
        float sv = __ldg(srow + s2);
        const float4* wr = (const float4*)(W1 + (3 + s2) * HID) + half*8;
        #pragma unroll
        for (int g = 0; g < 8; g++) {
          float4 w = __ldg(wr + g);
          acc[g].x = fmaf(sv, w.x, acc[g].x);
          acc[g].y = fmaf(sv, w.y, acc[g].y);
          acc[g].z = fmaf(sv, w.z, acc[g].z);
          acc[g].w = fmaf(sv, w.w, acc[g].w);
        }
      }
      #pragma unroll
      for (int g = 0; g < 8; g++) {
        int j = half*32 + 4*g;
        sS1[(j + 0)*TPB + tid] = acc[g].x;
        sS1[(j + 1)*TPB + tid] = acc[g].y;
        sS1[(j + 2)*TPB + tid] = acc[g].z;
        sS1[(j + 3)*TPB + tid] = acc[g].w;
      }
    }
  }

  // ---- integrate ----
  float y0 = __ldg(pad0 + (size_t)row*3 + 0);
  float y1 = __ldg(pad0 + (size_t)row*3 + 1);
  float y2 = __ldg(pad0 + (size_t)row*3 + 2);
  const float sc = __ldg(scale);
  const float h = 1.0f / (float)NSTEPS;

  float k[6][3];

  #pragma unroll 1
  for (int st = 0; st < NSTEPS; st++) {
    float t0 = (float)st * h;

    #pragma unroll 1
    for (int s = 0; s < 6; s++) {
      float ys0 = y0, ys1 = y1, ys2 = y2;
      #pragma unroll
      for (int m = 0; m < 5; m++) {
        if (m < s) {
          float a = h * c_A[s][m];
          ys0 = fmaf(a, k[m][0], ys0);
          ys1 = fmaf(a, k[m][1], ys1);
          ys2 = fmaf(a, k[m][2], ys2);
        }
      }
      float ts = fmaf(c_C[s], h, t0);
      const u64 ya = pk2(ys0, ys1);
      const u64 yb = pk2(ys2, ts);

      // ---- init packed accumulators a2[j] = (b2[2j], b2[2j+1]) ----
      u64 a2[HID/2];
      {
        const ulonglong2* b2p = (const ulonglong2*)sB2;
        #pragma unroll
        for (int g = 0; g < HID/4; g++) {
          ulonglong2 v = b2p[g];
          a2[2*g + 0] = v.x;
          a2[2*g + 1] = v.y;
        }
      }

      // ---- fused layer1 + layer2 accumulation over hidden i ----
      #pragma unroll 2
      for (int i = 0; i < HID; i++) {
        ulonglong2 wy = ((const ulonglong2*)sW1y)[i];   // (w0,w1),(w2,wt)
        u64 p2 = mul2(ya, wy.x);
        p2 = fma2(yb, wy.y, p2);
        float plo, phi; upk2(p2, plo, phi);
        float pre = (sS1[i*TPB + tid] + plo) + phi;
        float hv = ftanh(pre);
        u64 hv2 = pk2(hv, hv);
        const ulonglong2* w2r = (const ulonglong2*)(sW2 + i*HID);
        #pragma unroll
        for (int g = 0; g < HID/4; g++) {
          ulonglong2 w = w2r[g];
          a2[2*g + 0] = fma2(hv2, w.x, a2[2*g + 0]);
          a2[2*g + 1] = fma2(hv2, w.y, a2[2*g + 1]);
        }
      }

      // ---- layer2 tanh + layer3 (packed even/odd accumulation) ----
      u64 o0p = 0, o1p = 0, o2p = 0;   // 0x0 == (0.0f, 0.0f)
      const u64* t0p = (const u64*)(sW3T + 0*HID);
      const u64* t1p = (const u64*)(sW3T + 1*HID);
      const u64* t2p = (const u64*)(sW3T + 2*HID);
      #pragma unroll 4
      for (int j = 0; j < HID/2; j++) {
        float plo, phi; upk2(a2[j], plo, phi);
        u64 hp = pk2(ftanh(plo), ftanh(phi));
        o0p = fma2(hp, t0p[j], o0p);
        o1p = fma2(hp, t1p[j], o1p);
        o2p = fma2(hp, t2p[j], o2p);
      }
      float e, o;
      upk2(o0p, e, o); float v0 = (sB3[0] + e) + o;
      upk2(o1p, e, o); float v1 = (sB3[1] + e) + o;
      upk2(o2p, e, o); float v2 = (sB3[2] + e) + o;

      k[s][0] = ftanh(v0) * sc;
      k[s][1] = ftanh(v1) * sc;
      k[s][2] = ftanh(v2) * sc;
    }

    #pragma unroll
    for (int m = 0; m < 6; m++) {
      float bm = h * c_B[m];
      y0 = fmaf(bm, k[m][0], y0);
      y1 = fmaf(bm, k[m][1], y1);
      y2 = fmaf(bm, k[m][2], y2);
    }
  }

  out[(size_t)row*3 + 0] = y0;
  out[(size_t)row*3 + 1] = y1;
  out[(size_t)row*3 + 2] = y2;
}

extern "C" void kernel_launch(void* const* d_in, const int* in_sizes, int n_in,
                              void* d_out, int out_size) {
  const float* pad0  = (const float*)d_in[0];
  const float* sens  = (const float*)d_in[1];
  const float* W1    = (const float*)d_in[2];
  const float* b1    = (const float*)d_in[3];
  const float* W2    = (const float*)d_in[4];
  const float* b2    = (const float*)d_in[5];
  const float* W3    = (const float*)d_in[6];
  const float* b3    = (const float*)d_in[7];
  const float* scale = (const float*)d_in[8];
  float* out = (float*)d_out;

  const int nrows = in_sizes[0] / 3;
  const int smem_bytes = SMEM_FLOATS * (int)sizeof(float);
  cudaFuncSetAttribute(ode_kernel, cudaFuncAttributeMaxDynamicSharedMemorySize, smem_bytes);

  const int grid = (nrows + TPB - 1) / TPB;
  ode_kernel<<<grid, TPB, smem_bytes>>>(pad0, sens, W1, b1, W2, b2, W3, b3, scale, out, nrows);
}

// round 4
// speedup vs baseline: 1.2111x; 1.2111x over previous
#include <cuda_runtime.h>

#define SENS 61
#define HID  64
#define NSTEPS 10
#define TPB  128

typedef unsigned long long u64;

// Dormand–Prince 5(4) tableau
__constant__ float c_A[6][5] = {
  {0.f, 0.f, 0.f, 0.f, 0.f},
  {(float)(1.0/5.0), 0.f, 0.f, 0.f, 0.f},
  {(float)(3.0/40.0), (float)(9.0/40.0), 0.f, 0.f, 0.f},
  {(float)(44.0/45.0), (float)(-56.0/15.0), (float)(32.0/9.0), 0.f, 0.f},
  {(float)(19372.0/6561.0), (float)(-25360.0/2187.0), (float)(64448.0/6561.0), (float)(-212.0/729.0), 0.f},
  {(float)(9017.0/3168.0), (float)(-355.0/33.0), (float)(46732.0/5247.0), (float)(49.0/176.0), (float)(-5103.0/18656.0)}
};
__constant__ float c_C[6] = {0.f, 0.2f, 0.3f, 0.8f, (float)(8.0/9.0), 1.f};
__constant__ float c_B[6] = {(float)(35.0/384.0), 0.f, (float)(500.0/1113.0),
                             (float)(125.0/192.0), (float)(-2187.0/6784.0), (float)(11.0/84.0)};

// ---- packed f32x2 + fast tanh helpers ----
__device__ __forceinline__ float ftanh(float x) {
  float r; asm("tanh.approx.f32 %0, %1;" : "=f"(r) : "f"(x)); return r;
}
__device__ __forceinline__ u64 pk2(float lo, float hi) {
  u64 r; asm("mov.b64 %0, {%1, %2};" : "=l"(r) : "f"(lo), "f"(hi)); return r;
}
__device__ __forceinline__ void upk2(u64 v, float& lo, float& hi) {
  asm("mov.b64 {%0, %1}, %2;" : "=f"(lo), "=f"(hi) : "l"(v));
}
__device__ __forceinline__ u64 fma2(u64 a, u64 b, u64 c) {
  u64 d; asm("fma.rn.f32x2 %0, %1, %2, %3;" : "=l"(d) : "l"(a), "l"(b), "l"(c)); return d;
}

// Shared layout (floats):
//   sW1y : [64][4]   rows {W1[0],W1[1],W1[2],W1[64]} transposed (y + t weights)
//   sW2  : [64][64]
//   sW3T : [3][64]   transposed W3 (row c = W3[:,c])
//   sB2  : [64]
//   sB3  : [4]
//   sS1  : [64][TPB] per-thread sensory contribution incl. b1
#define OFF_W1Y 0
#define OFF_W2  (OFF_W1Y + HID*4)
#define OFF_W3T (OFF_W2 + HID*HID)
#define OFF_B2  (OFF_W3T + 4*HID)
#define OFF_B3  (OFF_B2 + HID)
#define OFF_S1  (OFF_B3 + 4)
#define SMEM_FLOATS (OFF_S1 + HID*TPB)

__global__ void __launch_bounds__(TPB, 2)
ode_kernel(const float* __restrict__ pad0, const float* __restrict__ sens,
           const float* __restrict__ W1, const float* __restrict__ b1,
           const float* __restrict__ W2, const float* __restrict__ b2,
           const float* __restrict__ W3, const float* __restrict__ b3,
           const float* __restrict__ scale, float* __restrict__ out, int nrows)
{
  extern __shared__ float sm[];
  float* sW1y = sm + OFF_W1Y;
  float* sW2  = sm + OFF_W2;
  float* sW3T = sm + OFF_W3T;
  float* sB2  = sm + OFF_B2;
  float* sB3  = sm + OFF_B3;
  float* sS1  = sm + OFF_S1;

  const int tid = threadIdx.x;

  // ---- cooperative weight staging ----
  for (int j = tid; j < HID; j += TPB) {
    sW1y[j*4 + 0] = W1[0*HID + j];
    sW1y[j*4 + 1] = W1[1*HID + j];
    sW1y[j*4 + 2] = W1[2*HID + j];
    sW1y[j*4 + 3] = W1[64*HID + j];   // time row
  }
  for (int idx = tid; idx < HID*HID; idx += TPB) sW2[idx] = W2[idx];
  for (int j = tid; j < HID; j += TPB) {
    sW3T[0*HID + j] = W3[j*3 + 0];
    sW3T[1*HID + j] = W3[j*3 + 1];
    sW3T[2*HID + j] = W3[j*3 + 2];
    sB2[j] = b2[j];
  }
  if (tid < 4) sB3[tid] = (tid < 3) ? b3[tid] : 0.0f;
  __syncthreads();

  const int row = blockIdx.x * TPB + tid;
  if (row >= nrows) return;

  // ---- prologue: s1[j] = b1[j] + sensory . W1[3:64, j]  (constant over 60 evals) ----
  {
    const float* srow = sens + (size_t)row * SENS;
    #pragma unroll
    for (int half = 0; half < 2; half++) {
      float4 acc[8];
      const float4* b1v = (const float4*)b1;
      #pragma unroll
      for (int g = 0; g < 8; g++) acc[g] = __ldg(b1v + half*8 + g);
      for (int s2 = 0; s2 < SENS; s2++) {
        float sv = __ldg(srow + s2);
        const float4* wr = (const float4*)(W1 + (3 + s2) * HID) + half*8;
        #pragma unroll
        for (int g = 0; g < 8; g++) {
          float4 w = __ldg(wr + g);
          acc[g].x = fmaf(sv, w.x, acc[g].x);
          acc[g].y = fmaf(sv, w.y, acc[g].y);
          acc[g].z = fmaf(sv, w.z, acc[g].z);
          acc[g].w = fmaf(sv, w.w, acc[g].w);
        }
      }
      #pragma unroll
      for (int g = 0; g < 8; g++) {
        int j = half*32 + 4*g;
        sS1[(j + 0)*TPB + tid] = acc[g].x;
        sS1[(j + 1)*TPB + tid] = acc[g].y;
        sS1[(j + 2)*TPB + tid] = acc[g].z;
        sS1[(j + 3)*TPB + tid] = acc[g].w;
      }
    }
  }

  // ---- integrate ----
  float y0 = __ldg(pad0 + (size_t)row*3 + 0);
  float y1 = __ldg(pad0 + (size_t)row*3 + 1);
  float y2 = __ldg(pad0 + (size_t)row*3 + 2);
  const float sc = __ldg(scale);
  const float h = 1.0f / (float)NSTEPS;

  float k[6][3];

  #pragma unroll 1
  for (int st = 0; st < NSTEPS; st++) {
    float t0 = (float)st * h;

    #pragma unroll 1
    for (int s = 0; s < 6; s++) {
      float ys0 = y0, ys1 = y1, ys2 = y2;
      #pragma unroll
      for (int m = 0; m < 5; m++) {
        if (m < s) {
          float a = h * c_A[s][m];
          ys0 = fmaf(a, k[m][0], ys0);
          ys1 = fmaf(a, k[m][1], ys1);
          ys2 = fmaf(a, k[m][2], ys2);
        }
      }
      float ts = fmaf(c_C[s], h, t0);

      // ---- init packed accumulators a2[g] = (b2[2g], b2[2g+1]) ----
      u64 a2[HID/2];
      {
        const ulonglong2* b2p = (const ulonglong2*)sB2;
        #pragma unroll
        for (int g = 0; g < HID/4; g++) {
          ulonglong2 v = b2p[g];
          a2[2*g + 0] = v.x;
          a2[2*g + 1] = v.y;
        }
      }

      // ---- fused layer1 (scalar) + layer2 (packed) over hidden i ----
      #pragma unroll 2
      for (int i = 0; i < HID; i++) {
        const float4 wy = ((const float4*)sW1y)[i];
        float pre = sS1[i*TPB + tid];
        pre = fmaf(ys0, wy.x, pre);
        pre = fmaf(ys1, wy.y, pre);
        pre = fmaf(ys2, wy.z, pre);
        pre = fmaf(ts,  wy.w, pre);
        float hv = ftanh(pre);
        u64 hv2 = pk2(hv, hv);                          // splat: 1 mov per i
        const ulonglong2* w2r = (const ulonglong2*)(sW2 + i*HID);
        #pragma unroll
        for (int g = 0; g < HID/4; g++) {
          ulonglong2 w = w2r[g];                        // LDS.128 -> two u64 halves
          a2[2*g + 0] = fma2(hv2, w.x, a2[2*g + 0]);
          a2[2*g + 1] = fma2(hv2, w.y, a2[2*g + 1]);
        }
      }

      // ---- layer2 tanh + layer3 (packed over j-pairs) ----
      u64 o0p = 0, o1p = 0, o2p = 0;                    // (0.0f, 0.0f)
      const u64* t0p = (const u64*)(sW3T + 0*HID);
      const u64* t1p = (const u64*)(sW3T + 1*HID);
      const u64* t2p = (const u64*)(sW3T + 2*HID);
      #pragma unroll 8
      for (int j = 0; j < HID/2; j++) {
        float plo, phi; upk2(a2[j], plo, phi);
        u64 hp = pk2(ftanh(plo), ftanh(phi));
        o0p = fma2(hp, t0p[j], o0p);
        o1p = fma2(hp, t1p[j], o1p);
        o2p = fma2(hp, t2p[j], o2p);
      }
      float e, o;
      upk2(o0p, e, o); float v0 = (sB3[0] + e) + o;
      upk2(o1p, e, o); float v1 = (sB3[1] + e) + o;
      upk2(o2p, e, o); float v2 = (sB3[2] + e) + o;

      k[s][0] = ftanh(v0) * sc;
      k[s][1] = ftanh(v1) * sc;
      k[s][2] = ftanh(v2) * sc;
    }

    #pragma unroll
    for (int m = 0; m < 6; m++) {
      float bm = h * c_B[m];
      y0 = fmaf(bm, k[m][0], y0);
      y1 = fmaf(bm, k[m][1], y1);
      y2 = fmaf(bm, k[m][2], y2);
    }
  }

  out[(size_t)row*3 + 0] = y0;
  out[(size_t)row*3 + 1] = y1;
  out[(size_t)row*3 + 2] = y2;
}

extern "C" void kernel_launch(void* const* d_in, const int* in_sizes, int n_in,
                              void* d_out, int out_size) {
  const float* pad0  = (const float*)d_in[0];
  const float* sens  = (const float*)d_in[1];
  const float* W1    = (const float*)d_in[2];
  const float* b1    = (const float*)d_in[3];
  const float* W2    = (const float*)d_in[4];
  const float* b2    = (const float*)d_in[5];
  const float* W3    = (const float*)d_in[6];
  const float* b3    = (const float*)d_in[7];
  const float* scale = (const float*)d_in[8];
  float* out = (float*)d_out;

  const int nrows = in_sizes[0] / 3;
  const int smem_bytes = SMEM_FLOATS * (int)sizeof(float);
  cudaFuncSetAttribute(ode_kernel, cudaFuncAttributeMaxDynamicSharedMemorySize, smem_bytes);

  const int grid = (nrows + TPB - 1) / TPB;
  ode_kernel<<<grid, TPB, smem_bytes>>>(pad0, sens, W1, b1, W2, b2, W3, b3, scale, out, nrows);
}

// round 5
// speedup vs baseline: 1.3407x; 1.1070x over previous
#include <cuda_runtime.h>

#define SENS 61
#define HID  64
#define NSTEPS 10
#define TPB  128
#define ROWS_PER_T 2

typedef unsigned long long u64;

// Dormand–Prince 5(4) tableau
__constant__ float c_A[6][5] = {
  {0.f, 0.f, 0.f, 0.f, 0.f},
  {(float)(1.0/5.0), 0.f, 0.f, 0.f, 0.f},
  {(float)(3.0/40.0), (float)(9.0/40.0), 0.f, 0.f, 0.f},
  {(float)(44.0/45.0), (float)(-56.0/15.0), (float)(32.0/9.0), 0.f, 0.f},
  {(float)(19372.0/6561.0), (float)(-25360.0/2187.0), (float)(64448.0/6561.0), (float)(-212.0/729.0), 0.f},
  {(float)(9017.0/3168.0), (float)(-355.0/33.0), (float)(46732.0/5247.0), (float)(49.0/176.0), (float)(-5103.0/18656.0)}
};
__constant__ float c_C[6] = {0.f, 0.2f, 0.3f, 0.8f, (float)(8.0/9.0), 1.f};
__constant__ float c_B[6] = {(float)(35.0/384.0), 0.f, (float)(500.0/1113.0),
                             (float)(125.0/192.0), (float)(-2187.0/6784.0), (float)(11.0/84.0)};

// ---- packed f32x2 + fast tanh helpers ----
__device__ __forceinline__ float ftanh(float x) {
  float r; asm("tanh.approx.f32 %0, %1;" : "=f"(r) : "f"(x)); return r;
}
__device__ __forceinline__ u64 pk2(float lo, float hi) {
  u64 r; asm("mov.b64 %0, {%1, %2};" : "=l"(r) : "f"(lo), "f"(hi)); return r;
}
__device__ __forceinline__ void upk2(u64 v, float& lo, float& hi) {
  asm("mov.b64 {%0, %1}, %2;" : "=f"(lo), "=f"(hi) : "l"(v));
}
__device__ __forceinline__ u64 fma2(u64 a, u64 b, u64 c) {
  u64 d; asm("fma.rn.f32x2 %0, %1, %2, %3;" : "=l"(d) : "l"(a), "l"(b), "l"(c)); return d;
}

// Shared layout (floats):
//   sW1y : [64][4]      rows {W1[0],W1[1],W1[2],W1[64]} transposed (y + t weights)
//   sW2  : [64][64]
//   sW3T : [3][64]      transposed W3
//   sB2  : [64]
//   sB3  : [4]
//   sS1  : [64][TPB] of u64: packed (s1_row0, s1_row1) per thread
#define OFF_W1Y 0
#define OFF_W2  (OFF_W1Y + HID*4)
#define OFF_W3T (OFF_W2 + HID*HID)
#define OFF_B2  (OFF_W3T + 4*HID)
#define OFF_B3  (OFF_B2 + HID)
#define OFF_S1  (OFF_B3 + 4)                      // 8-byte aligned (total so far even)
#define SMEM_FLOATS (OFF_S1 + HID*TPB*2)

__global__ void __launch_bounds__(TPB, 2)
ode_kernel(const float* __restrict__ pad0, const float* __restrict__ sens,
           const float* __restrict__ W1, const float* __restrict__ b1,
           const float* __restrict__ W2, const float* __restrict__ b2,
           const float* __restrict__ W3, const float* __restrict__ b3,
           const float* __restrict__ scale, float* __restrict__ out, int nrows)
{
  extern __shared__ float sm[];
  float* sW1y = sm + OFF_W1Y;
  float* sW2  = sm + OFF_W2;
  float* sW3T = sm + OFF_W3T;
  float* sB2  = sm + OFF_B2;
  float* sB3  = sm + OFF_B3;
  u64*   sS1  = (u64*)(sm + OFF_S1);

  const int tid = threadIdx.x;

  // ---- cooperative weight staging ----
  for (int j = tid; j < HID; j += TPB) {
    sW1y[j*4 + 0] = W1[0*HID + j];
    sW1y[j*4 + 1] = W1[1*HID + j];
    sW1y[j*4 + 2] = W1[2*HID + j];
    sW1y[j*4 + 3] = W1[64*HID + j];   // time row
  }
  for (int idx = tid; idx < HID*HID; idx += TPB) sW2[idx] = W2[idx];
  for (int j = tid; j < HID; j += TPB) {
    sW3T[0*HID + j] = W3[j*3 + 0];
    sW3T[1*HID + j] = W3[j*3 + 1];
    sW3T[2*HID + j] = W3[j*3 + 2];
    sB2[j] = b2[j];
  }
  if (tid < 4) sB3[tid] = (tid < 3) ? b3[tid] : 0.0f;
  __syncthreads();

  // two rows per thread, adjacent for global-access locality
  const long r0 = (long)(blockIdx.x * TPB + tid) * 2;
  const long r1 = r0 + 1;
  if (r0 >= nrows) return;

  // ---- prologue: s1[j] = b1[j] + sensory . W1[3:64, j]  (both rows, packed store) ----
  {
    const float* srow0 = sens + r0 * SENS;
    const float* srow1 = sens + r1 * SENS;
    #pragma unroll
    for (int half = 0; half < 2; half++) {
      float4 a0[8], a1[8];
      const float4* b1v = (const float4*)b1;
      #pragma unroll
      for (int g = 0; g < 8; g++) { a0[g] = __ldg(b1v + half*8 + g); a1[g] = a0[g]; }
      for (int s2 = 0; s2 < SENS; s2++) {
        float sv0 = __ldg(srow0 + s2);
        float sv1 = __ldg(srow1 + s2);
        const float4* wr = (const float4*)(W1 + (3 + s2) * HID) + half*8;
        #pragma unroll
        for (int g = 0; g < 8; g++) {
          float4 w = __ldg(wr + g);
          a0[g].x = fmaf(sv0, w.x, a0[g].x);  a1[g].x = fmaf(sv1, w.x, a1[g].x);
          a0[g].y = fmaf(sv0, w.y, a0[g].y);  a1[g].y = fmaf(sv1, w.y, a1[g].y);
          a0[g].z = fmaf(sv0, w.z, a0[g].z);  a1[g].z = fmaf(sv1, w.z, a1[g].z);
          a0[g].w = fmaf(sv0, w.w, a0[g].w);  a1[g].w = fmaf(sv1, w.w, a1[g].w);
        }
      }
      #pragma unroll
      for (int g = 0; g < 8; g++) {
        int j = half*32 + 4*g;
        sS1[(j + 0)*TPB + tid] = pk2(a0[g].x, a1[g].x);
        sS1[(j + 1)*TPB + tid] = pk2(a0[g].y, a1[g].y);
        sS1[(j + 2)*TPB + tid] = pk2(a0[g].z, a1[g].z);
        sS1[(j + 3)*TPB + tid] = pk2(a0[g].w, a1[g].w);
      }
    }
  }

  // ---- integrate both rows ----
  float ya0 = __ldg(pad0 + r0*3 + 0), ya1 = __ldg(pad0 + r0*3 + 1), ya2 = __ldg(pad0 + r0*3 + 2);
  float yb0 = __ldg(pad0 + r1*3 + 0), yb1 = __ldg(pad0 + r1*3 + 1), yb2 = __ldg(pad0 + r1*3 + 2);
  const float sc = __ldg(scale);
  const float h = 1.0f / (float)NSTEPS;

  float ka[6][3], kb[6][3];

  #pragma unroll 1
  for (int st = 0; st < NSTEPS; st++) {
    float t0 = (float)st * h;

    #pragma unroll 1
    for (int s = 0; s < 6; s++) {
      float p0 = ya0, p1 = ya1, p2 = ya2;
      float q0 = yb0, q1 = yb1, q2 = yb2;
      #pragma unroll
      for (int m = 0; m < 5; m++) {
        if (m < s) {
          float a = h * c_A[s][m];
          p0 = fmaf(a, ka[m][0], p0); p1 = fmaf(a, ka[m][1], p1); p2 = fmaf(a, ka[m][2], p2);
          q0 = fmaf(a, kb[m][0], q0); q1 = fmaf(a, kb[m][1], q1); q2 = fmaf(a, kb[m][2], q2);
        }
      }
      float ts = fmaf(c_C[s], h, t0);

      // ---- init packed accumulators (j-pairs) for each row ----
      u64 accA[HID/2], accB[HID/2];
      {
        const ulonglong2* b2p = (const ulonglong2*)sB2;
        #pragma unroll
        for (int g = 0; g < HID/4; g++) {
          ulonglong2 v = b2p[g];
          accA[2*g+0] = v.x;  accB[2*g+0] = v.x;
          accA[2*g+1] = v.y;  accB[2*g+1] = v.y;
        }
      }

      // ---- fused layer1 (scalar, both rows) + layer2 (packed, shared weights) ----
      #pragma unroll 2
      for (int i = 0; i < HID; i++) {
        const float4 wy = ((const float4*)sW1y)[i];
        float s1a, s1b; upk2(sS1[i*TPB + tid], s1a, s1b);
        float preA = fmaf(p0, wy.x, s1a);
        preA = fmaf(p1, wy.y, preA);
        preA = fmaf(p2, wy.z, preA);
        preA = fmaf(ts, wy.w, preA);
        float preB = fmaf(q0, wy.x, s1b);
        preB = fmaf(q1, wy.y, preB);
        preB = fmaf(q2, wy.z, preB);
        preB = fmaf(ts, wy.w, preB);
        float hvA = ftanh(preA);
        float hvB = ftanh(preB);
        u64 hA = pk2(hvA, hvA);
        u64 hB = pk2(hvB, hvB);
        const ulonglong2* w2r = (const ulonglong2*)(sW2 + i*HID);
        #pragma unroll
        for (int g = 0; g < HID/4; g++) {
          ulonglong2 w = w2r[g];                 // one LDS.128 serves both rows
          accA[2*g+0] = fma2(hA, w.x, accA[2*g+0]);
          accB[2*g+0] = fma2(hB, w.x, accB[2*g+0]);
          accA[2*g+1] = fma2(hA, w.y, accA[2*g+1]);
          accB[2*g+1] = fma2(hB, w.y, accB[2*g+1]);
        }
      }

      // ---- layer2 tanh + layer3 (packed over j-pairs), row A then row B ----
      const u64* t0p = (const u64*)(sW3T + 0*HID);
      const u64* t1p = (const u64*)(sW3T + 1*HID);
      const u64* t2p = (const u64*)(sW3T + 2*HID);
      {
        u64 o0 = 0, o1 = 0, o2 = 0;
        #pragma unroll 8
        for (int j = 0; j < HID/2; j++) {
          float lo, hi; upk2(accA[j], lo, hi);
          u64 hp = pk2(ftanh(lo), ftanh(hi));
          o0 = fma2(hp, t0p[j], o0);
          o1 = fma2(hp, t1p[j], o1);
          o2 = fma2(hp, t2p[j], o2);
        }
        float e, o;
        upk2(o0, e, o); ka[s][0] = ftanh((sB3[0] + e) + o) * sc;
        upk2(o1, e, o); ka[s][1] = ftanh((sB3[1] + e) + o) * sc;
        upk2(o2, e, o); ka[s][2] = ftanh((sB3[2] + e) + o) * sc;
      }
      {
        u64 o0 = 0, o1 = 0, o2 = 0;
        #pragma unroll 8
        for (int j = 0; j < HID/2; j++) {
          float lo, hi; upk2(accB[j], lo, hi);
          u64 hp = pk2(ftanh(lo), ftanh(hi));
          o0 = fma2(hp, t0p[j], o0);
          o1 = fma2(hp, t1p[j], o1);
          o2 = fma2(hp, t2p[j], o2);
        }
        float e, o;
        upk2(o0, e, o); kb[s][0] = ftanh((sB3[0] + e) + o) * sc;
        upk2(o1, e, o); kb[s][1] = ftanh((sB3[1] + e) + o) * sc;
        upk2(o2, e, o); kb[s][2] = ftanh((sB3[2] + e) + o) * sc;
      }
    }

    #pragma unroll
    for (int m = 0; m < 6; m++) {
      float bm = h * c_B[m];
      ya0 = fmaf(bm, ka[m][0], ya0); ya1 = fmaf(bm, ka[m][1], ya1); ya2 = fmaf(bm, ka[m][2], ya2);
      yb0 = fmaf(bm, kb[m][0], yb0); yb1 = fmaf(bm, kb[m][1], yb1); yb2 = fmaf(bm, kb[m][2], yb2);
    }
  }

  out[r0*3 + 0] = ya0;  out[r0*3 + 1] = ya1;  out[r0*3 + 2] = ya2;
  out[r1*3 + 0] = yb0;  out[r1*3 + 1] = yb1;  out[r1*3 + 2] = yb2;
}

extern "C" void kernel_launch(void* const* d_in, const int* in_sizes, int n_in,
                              void* d_out, int out_size) {
  const float* pad0  = (const float*)d_in[0];
  const float* sens  = (const float*)d_in[1];
  const float* W1    = (const float*)d_in[2];
  const float* b1    = (const float*)d_in[3];
  const float* W2    = (const float*)d_in[4];
  const float* b2    = (const float*)d_in[5];
  const float* W3    = (const float*)d_in[6];
  const float* b3    = (const float*)d_in[7];
  const float* scale = (const float*)d_in[8];
  float* out = (float*)d_out;

  const int nrows = in_sizes[0] / 3;
  const int smem_bytes = SMEM_FLOATS * (int)sizeof(float);
  cudaFuncSetAttribute(ode_kernel, cudaFuncAttributeMaxDynamicSharedMemorySize, smem_bytes);

  const int rows_per_blk = TPB * ROWS_PER_T;
  const int grid = (nrows + rows_per_blk - 1) / rows_per_blk;
  ode_kernel<<<grid, TPB, smem_bytes>>>(pad0, sens, W1, b1, W2, b2, W3, b3, scale, out, nrows);
}

// round 6
// speedup vs baseline: 1.4603x; 1.0892x over previous
#include <cuda_runtime.h>

#define SENS 61
#define HID  64
#define NSTEPS 10
#define TPB  128
#define ROWS_PER_T 2

typedef unsigned long long u64;

// Dormand–Prince 5(4) tableau
__constant__ float c_A[6][5] = {
  {0.f, 0.f, 0.f, 0.f, 0.f},
  {(float)(1.0/5.0), 0.f, 0.f, 0.f, 0.f},
  {(float)(3.0/40.0), (float)(9.0/40.0), 0.f, 0.f, 0.f},
  {(float)(44.0/45.0), (float)(-56.0/15.0), (float)(32.0/9.0), 0.f, 0.f},
  {(float)(19372.0/6561.0), (float)(-25360.0/2187.0), (float)(64448.0/6561.0), (float)(-212.0/729.0), 0.f},
  {(float)(9017.0/3168.0), (float)(-355.0/33.0), (float)(46732.0/5247.0), (float)(49.0/176.0), (float)(-5103.0/18656.0)}
};
__constant__ float c_C[6] = {0.f, 0.2f, 0.3f, 0.8f, (float)(8.0/9.0), 1.f};
__constant__ float c_B[6] = {(float)(35.0/384.0), 0.f, (float)(500.0/1113.0),
                             (float)(125.0/192.0), (float)(-2187.0/6784.0), (float)(11.0/84.0)};

// ---- packed f32x2 + fast tanh helpers ----
__device__ __forceinline__ float ftanh(float x) {
  float r; asm("tanh.approx.f32 %0, %1;" : "=f"(r) : "f"(x)); return r;
}
__device__ __forceinline__ u64 pk2(float lo, float hi) {
  u64 r; asm("mov.b64 %0, {%1, %2};" : "=l"(r) : "f"(lo), "f"(hi)); return r;
}
__device__ __forceinline__ void upk2(u64 v, float& lo, float& hi) {
  asm("mov.b64 {%0, %1}, %2;" : "=f"(lo), "=f"(hi) : "l"(v));
}
__device__ __forceinline__ u64 fma2(u64 a, u64 b, u64 c) {
  u64 d; asm("fma.rn.f32x2 %0, %1, %2, %3;" : "=l"(d) : "l"(a), "l"(b), "l"(c)); return d;
}

// Shared layout (floats):
//   sW1y : [64][4]        rows {W1[0],W1[1],W1[2],W1[64]} transposed
//   sW2  : [64][64]
//   sW3T : [3][64]        transposed W3
//   sB2  : [64]
//   sB3  : [4]
//   sS1p : [32][TPB] of ulonglong2:  ((s1[2m],s1r1[2m]),(s1[2m+1],s1r1[2m+1]))
#define OFF_W1Y 0
#define OFF_W2  (OFF_W1Y + HID*4)
#define OFF_W3T (OFF_W2 + HID*HID)
#define OFF_B2  (OFF_W3T + 4*HID)
#define OFF_B3  (OFF_B2 + HID)
#define OFF_S1  (OFF_B3 + 4)                    // *4B = 16-byte aligned
#define SMEM_FLOATS (OFF_S1 + HID*TPB*2)

__global__ void __launch_bounds__(TPB)
ode_kernel(const float* __restrict__ pad0, const float* __restrict__ sens,
           const float* __restrict__ W1, const float* __restrict__ b1,
           const float* __restrict__ W2, const float* __restrict__ b2,
           const float* __restrict__ W3, const float* __restrict__ b3,
           const float* __restrict__ scale, float* __restrict__ out, int nrows)
{
  extern __shared__ float sm[];
  float* sW1y = sm + OFF_W1Y;
  float* sW2  = sm + OFF_W2;
  float* sW3T = sm + OFF_W3T;
  float* sB2  = sm + OFF_B2;
  float* sB3  = sm + OFF_B3;
  ulonglong2* sS1p = (ulonglong2*)(sm + OFF_S1);

  const int tid = threadIdx.x;

  // ---- cooperative weight staging ----
  for (int j = tid; j < HID; j += TPB) {
    sW1y[j*4 + 0] = W1[0*HID + j];
    sW1y[j*4 + 1] = W1[1*HID + j];
    sW1y[j*4 + 2] = W1[2*HID + j];
    sW1y[j*4 + 3] = W1[64*HID + j];   // time row
  }
  for (int idx = tid; idx < HID*HID; idx += TPB) sW2[idx] = W2[idx];
  for (int j = tid; j < HID; j += TPB) {
    sW3T[0*HID + j] = W3[j*3 + 0];
    sW3T[1*HID + j] = W3[j*3 + 1];
    sW3T[2*HID + j] = W3[j*3 + 2];
    sB2[j] = b2[j];
  }
  if (tid < 4) sB3[tid] = (tid < 3) ? b3[tid] : 0.0f;
  __syncthreads();

  const long r0 = (long)(blockIdx.x * TPB + tid) * 2;
  const long r1 = r0 + 1;
  if (r0 >= nrows) return;

  // ---- prologue: s1[j] = b1[j] + sensory . W1[3:64, j]  (both rows, paired store) ----
  {
    const float* srow0 = sens + r0 * SENS;
    const float* srow1 = sens + r1 * SENS;
    #pragma unroll
    for (int half = 0; half < 2; half++) {
      float4 a0[8], a1[8];
      const float4* b1v = (const float4*)b1;
      #pragma unroll
      for (int g = 0; g < 8; g++) { a0[g] = __ldg(b1v + half*8 + g); a1[g] = a0[g]; }
      for (int s2 = 0; s2 < SENS; s2++) {
        float sv0 = __ldg(srow0 + s2);
        float sv1 = __ldg(srow1 + s2);
        const float4* wr = (const float4*)(W1 + (3 + s2) * HID) + half*8;
        #pragma unroll
        for (int g = 0; g < 8; g++) {
          float4 w = __ldg(wr + g);
          a0[g].x = fmaf(sv0, w.x, a0[g].x);  a1[g].x = fmaf(sv1, w.x, a1[g].x);
          a0[g].y = fmaf(sv0, w.y, a0[g].y);  a1[g].y = fmaf(sv1, w.y, a1[g].y);
          a0[g].z = fmaf(sv0, w.z, a0[g].z);  a1[g].z = fmaf(sv1, w.z, a1[g].z);
          a0[g].w = fmaf(sv0, w.w, a0[g].w);  a1[g].w = fmaf(sv1, w.w, a1[g].w);
        }
      }
      #pragma unroll
      for (int g = 0; g < 8; g++) {
        int j = half*32 + 4*g;              // j, j+1, j+2, j+3
        ulonglong2 v0; v0.x = pk2(a0[g].x, a1[g].x); v0.y = pk2(a0[g].y, a1[g].y);
        ulonglong2 v1; v1.x = pk2(a0[g].z, a1[g].z); v1.y = pk2(a0[g].w, a1[g].w);
        sS1p[(j>>1)*TPB + tid]     = v0;
        sS1p[((j>>1)+1)*TPB + tid] = v1;
      }
    }
  }

  // ---- integrate both rows ----
  float ya0 = __ldg(pad0 + r0*3 + 0), ya1 = __ldg(pad0 + r0*3 + 1), ya2 = __ldg(pad0 + r0*3 + 2);
  float yb0 = __ldg(pad0 + r1*3 + 0), yb1 = __ldg(pad0 + r1*3 + 1), yb2 = __ldg(pad0 + r1*3 + 2);
  const float sc = __ldg(scale);
  const float h = 1.0f / (float)NSTEPS;

  float ka[6][3], kb[6][3];

  #pragma unroll 1
  for (int st = 0; st < NSTEPS; st++) {
    float t0 = (float)st * h;

    #pragma unroll 1
    for (int s = 0; s < 6; s++) {
      float p0 = ya0, p1 = ya1, p2 = ya2;
      float q0 = yb0, q1 = yb1, q2 = yb2;
      #pragma unroll
      for (int m = 0; m < 5; m++) {
        if (m < s) {
          float a = h * c_A[s][m];
          p0 = fmaf(a, ka[m][0], p0); p1 = fmaf(a, ka[m][1], p1); p2 = fmaf(a, ka[m][2], p2);
          q0 = fmaf(a, kb[m][0], q0); q1 = fmaf(a, kb[m][1], q1); q2 = fmaf(a, kb[m][2], q2);
        }
      }
      float ts = fmaf(c_C[s], h, t0);

      // ---- init packed accumulators (j-pairs) per row ----
      u64 accA[HID/2], accB[HID/2];
      {
        const ulonglong2* b2p = (const ulonglong2*)sB2;
        #pragma unroll
        for (int g = 0; g < HID/4; g++) {
          ulonglong2 v = b2p[g];
          accA[2*g+0] = v.x;  accB[2*g+0] = v.x;
          accA[2*g+1] = v.y;  accB[2*g+1] = v.y;
        }
      }

      // ---- fused layer1 + layer2: blocks of 4 hidden units ----
      #pragma unroll 1
      for (int i = 0; i < HID; i += 4) {
        // batched sS1 loads: 2 x LDS.128 covers units i..i+3 for both rows
        ulonglong2 sA = sS1p[(i>>1)*TPB + tid];
        ulonglong2 sB = sS1p[((i>>1)+1)*TPB + tid];
        float s1a[4], s1b[4];
        upk2(sA.x, s1a[0], s1b[0]); upk2(sA.y, s1a[1], s1b[1]);
        upk2(sB.x, s1a[2], s1b[2]); upk2(sB.y, s1a[3], s1b[3]);

        // 8 independent layer-1 chains
        u64 hAp[4], hBp[4];
        #pragma unroll
        for (int u = 0; u < 4; u++) {
          const float4 wy = ((const float4*)sW1y)[i + u];
          float preA = fmaf(p0, wy.x, s1a[u]);
          float preB = fmaf(q0, wy.x, s1b[u]);
          preA = fmaf(p1, wy.y, preA);  preB = fmaf(q1, wy.y, preB);
          preA = fmaf(p2, wy.z, preA);  preB = fmaf(q2, wy.z, preB);
          preA = fmaf(ts, wy.w, preA);  preB = fmaf(ts, wy.w, preB);
          float hvA = ftanh(preA);
          float hvB = ftanh(preB);
          hAp[u] = pk2(hvA, hvA);
          hBp[u] = pk2(hvB, hvB);
        }

        // 4 interleaved W2 row-streams: per g, 4 LDS.128 + 16 fma2
        const ulonglong2* w0r = (const ulonglong2*)(sW2 + (i+0)*HID);
        const ulonglong2* w1r = (const ulonglong2*)(sW2 + (i+1)*HID);
        const ulonglong2* w2r = (const ulonglong2*)(sW2 + (i+2)*HID);
        const ulonglong2* w3r = (const ulonglong2*)(sW2 + (i+3)*HID);
        #pragma unroll
        for (int g = 0; g < HID/4; g++) {
          ulonglong2 w0 = w0r[g];
          ulonglong2 w1 = w1r[g];
          ulonglong2 w2v = w2r[g];
          ulonglong2 w3 = w3r[g];
          u64 tA0 = fma2(hAp[0], w0.x, accA[2*g+0]);
          u64 tB0 = fma2(hBp[0], w0.x, accB[2*g+0]);
          u64 tA1 = fma2(hAp[0], w0.y, accA[2*g+1]);
          u64 tB1 = fma2(hBp[0], w0.y, accB[2*g+1]);
          tA0 = fma2(hAp[1], w1.x, tA0);
          tB0 = fma2(hBp[1], w1.x, tB0);
          tA1 = fma2(hAp[1], w1.y, tA1);
          tB1 = fma2(hBp[1], w1.y, tB1);
          tA0 = fma2(hAp[2], w2v.x, tA0);
          tB0 = fma2(hBp[2], w2v.x, tB0);
          tA1 = fma2(hAp[2], w2v.y, tA1);
          tB1 = fma2(hBp[2], w2v.y, tB1);
          accA[2*g+0] = fma2(hAp[3], w3.x, tA0);
          accB[2*g+0] = fma2(hBp[3], w3.x, tB0);
          accA[2*g+1] = fma2(hAp[3], w3.y, tA1);
          accB[2*g+1] = fma2(hBp[3], w3.y, tB1);
        }
      }

      // ---- layer2 tanh + layer3 (packed over j-pairs), row A then row B ----
      const u64* t0p = (const u64*)(sW3T + 0*HID);
      const u64* t1p = (const u64*)(sW3T + 1*HID);
      const u64* t2p = (const u64*)(sW3T + 2*HID);
      {
        u64 o0 = 0, o1 = 0, o2 = 0;
        #pragma unroll 8
        for (int j = 0; j < HID/2; j++) {
          float lo, hi; upk2(accA[j], lo, hi);
          u64 hp = pk2(ftanh(lo), ftanh(hi));
          o0 = fma2(hp, t0p[j], o0);
          o1 = fma2(hp, t1p[j], o1);
          o2 = fma2(hp, t2p[j], o2);
        }
        float e, o;
        upk2(o0, e, o); ka[s][0] = ftanh((sB3[0] + e) + o) * sc;
        upk2(o1, e, o); ka[s][1] = ftanh((sB3[1] + e) + o) * sc;
        upk2(o2, e, o); ka[s][2] = ftanh((sB3[2] + e) + o) * sc;
      }
      {
        u64 o0 = 0, o1 = 0, o2 = 0;
        #pragma unroll 8
        for (int j = 0; j < HID/2; j++) {
          float lo, hi; upk2(accB[j], lo, hi);
          u64 hp = pk2(ftanh(lo), ftanh(hi));
          o0 = fma2(hp, t0p[j], o0);
          o1 = fma2(hp, t1p[j], o1);
          o2 = fma2(hp, t2p[j], o2);
        }
        float e, o;
        upk2(o0, e, o); kb[s][0] = ftanh((sB3[0] + e) + o) * sc;
        upk2(o1, e, o); kb[s][1] = ftanh((sB3[1] + e) + o) * sc;
        upk2(o2, e, o); kb[s][2] = ftanh((sB3[2] + e) + o) * sc;
      }
    }

    #pragma unroll
    for (int m = 0; m < 6; m++) {
      float bm = h * c_B[m];
      ya0 = fmaf(bm, ka[m][0], ya0); ya1 = fmaf(bm, ka[m][1], ya1); ya2 = fmaf(bm, ka[m][2], ya2);
      yb0 = fmaf(bm, kb[m][0], yb0); yb1 = fmaf(bm, kb[m][1], yb1); yb2 = fmaf(bm, kb[m][2], yb2);
    }
  }

  out[r0*3 + 0] = ya0;  out[r0*3 + 1] = ya1;  out[r0*3 + 2] = ya2;
  out[r1*3 + 0] = yb0;  out[r1*3 + 1] = yb1;  out[r1*3 + 2] = yb2;
}

extern "C" void kernel_launch(void* const* d_in, const int* in_sizes, int n_in,
                              void* d_out, int out_size) {
  const float* pad0  = (const float*)d_in[0];
  const float* sens  = (const float*)d_in[1];
  const float* W1    = (const float*)d_in[2];
  const float* b1    = (const float*)d_in[3];
  const float* W2    = (const float*)d_in[4];
  const float* b2    = (const float*)d_in[5];
  const float* W3    = (const float*)d_in[6];
  const float* b3    = (const float*)d_in[7];
  const float* scale = (const float*)d_in[8];
  float* out = (float*)d_out;

  const int nrows = in_sizes[0] / 3;
  const int smem_bytes = SMEM_FLOATS * (int)sizeof(float);
  cudaFuncSetAttribute(ode_kernel, cudaFuncAttributeMaxDynamicSharedMemorySize, smem_bytes);

  const int rows_per_blk = TPB * ROWS_PER_T;
  const int grid = (nrows + rows_per_blk - 1) / rows_per_blk;
  ode_kernel<<<grid, TPB, smem_bytes>>>(pad0, sens, W1, b1, W2, b2, W3, b3, scale, out, nrows);
}

// round 8
// speedup vs baseline: 4.5011x; 3.0823x over previous
#include <cuda_runtime.h>
#include <cuda_bf16.h>

#define SENS 61
#define HID  64
#define NSTEPS 10
#define TPB  128

typedef unsigned long long u64;
typedef unsigned int u32;

// Dormand–Prince 5(4) tableau
__constant__ float c_A[6][5] = {
  {0.f, 0.f, 0.f, 0.f, 0.f},
  {(float)(1.0/5.0), 0.f, 0.f, 0.f, 0.f},
  {(float)(3.0/40.0), (float)(9.0/40.0), 0.f, 0.f, 0.f},
  {(float)(44.0/45.0), (float)(-56.0/15.0), (float)(32.0/9.0), 0.f, 0.f},
  {(float)(19372.0/6561.0), (float)(-25360.0/2187.0), (float)(64448.0/6561.0), (float)(-212.0/729.0), 0.f},
  {(float)(9017.0/3168.0), (float)(-355.0/33.0), (float)(46732.0/5247.0), (float)(49.0/176.0), (float)(-5103.0/18656.0)}
};
__constant__ float c_C[6] = {0.f, 0.2f, 0.3f, 0.8f, (float)(8.0/9.0), 1.f};
__constant__ float c_Bw[6] = {(float)(35.0/384.0), 0.f, (float)(500.0/1113.0),
                              (float)(125.0/192.0), (float)(-2187.0/6784.0), (float)(11.0/84.0)};

// ---- helpers ----
__device__ __forceinline__ float ftanh(float x) {
  float r; asm("tanh.approx.f32 %0, %1;" : "=f"(r) : "f"(x)); return r;
}
__device__ __forceinline__ u64 pk2(float lo, float hi) {
  u64 r; asm("mov.b64 %0, {%1, %2};" : "=l"(r) : "f"(lo), "f"(hi)); return r;
}
__device__ __forceinline__ void upk2(u64 v, float& lo, float& hi) {
  asm("mov.b64 {%0, %1}, %2;" : "=f"(lo), "=f"(hi) : "l"(v));
}
__device__ __forceinline__ u64 fma2(u64 a, u64 b, u64 c) {
  u64 d; asm("fma.rn.f32x2 %0, %1, %2, %3;" : "=l"(d) : "l"(a), "l"(b), "l"(c)); return d;
}
__device__ __forceinline__ u32 bf16x2_of(float lo, float hi) {
  u32 r; asm("cvt.rn.bf16x2.f32 %0, %1, %2;" : "=r"(r) : "f"(hi), "f"(lo)); return r; // upper=hi, lower=lo
}
__device__ __forceinline__ u32 smem_u32(const void* p) {
  u32 a; asm("{ .reg .u64 t; cvta.to.shared.u64 t, %1; cvt.u32.u64 %0, t; }" : "=r"(a) : "l"(p));
  return a;
}
__device__ __forceinline__ void ldmx4(u32& r0, u32& r1, u32& r2, u32& r3, u32 addr) {
  asm volatile("ldmatrix.sync.aligned.m8n8.x4.shared.b16 {%0,%1,%2,%3}, [%4];"
               : "=r"(r0), "=r"(r1), "=r"(r2), "=r"(r3) : "r"(addr));
}
__device__ __forceinline__ void mma16816(float& d0, float& d1, float& d2, float& d3,
                                         u32 a0, u32 a1, u32 a2, u32 a3, u32 b0, u32 b1) {
  asm volatile("mma.sync.aligned.m16n8k16.row.col.f32.bf16.bf16.f32 "
               "{%0,%1,%2,%3}, {%4,%5,%6,%7}, {%8,%9}, {%0,%1,%2,%3};"
               : "+f"(d0), "+f"(d1), "+f"(d2), "+f"(d3)
               : "r"(a0), "r"(a1), "r"(a2), "r"(a3), "r"(b0), "r"(b1));
}

// smem byte offsets
#define OFF_A    0                          // 4 warps * 32 rows * 128B = 16384 (A-tile, bf16, swizzled)
#define OFF_S1   16384                      // float4[16][TPB] = 32768 (per-thread sensory term)
#define OFF_W1Y  (OFF_S1 + 32768)           // float4[64] = 1024
#define OFF_W3P  (OFF_W1Y + 1024)           // u64[8][4][3] = 768  (fragment-matched W3 pairs)
#define SMEM_BYTES (OFF_W3P + 768)

__global__ void __launch_bounds__(TPB)
ode_kernel(const float* __restrict__ pad0, const float* __restrict__ sens,
           const float* __restrict__ W1, const float* __restrict__ b1,
           const float* __restrict__ W2, const float* __restrict__ b2,
           const float* __restrict__ W3, const float* __restrict__ b3,
           const float* __restrict__ scale, float* __restrict__ out, int nrows)
{
  extern __shared__ char smem[];
  const u32 smem_base = smem_u32(smem);
  const int tid  = threadIdx.x;
  const int lane = tid & 31;
  const int wid  = tid >> 5;
  const int g    = lane >> 2;     // fragment group id
  const int t    = lane & 3;      // thread-in-group

  float* sW1y = (float*)(smem + OFF_W1Y);
  u64*   sW3P = (u64*)(smem + OFF_W3P);
  float4* sS1q = (float4*)(smem + OFF_S1);

  // ---- cooperative weight staging ----
  for (int j = tid; j < HID; j += TPB) {
    sW1y[j*4 + 0] = W1[0*HID + j];
    sW1y[j*4 + 1] = W1[1*HID + j];
    sW1y[j*4 + 2] = W1[2*HID + j];
    sW1y[j*4 + 3] = W1[64*HID + j];   // time row
  }
  // W3 fragment pairs: sW3P[(j*4+t)*3 + o] = (W3[8j+2t][o], W3[8j+2t+1][o])
  if (tid < 96) {
    int j = tid / 12, rem = tid % 12, tt = rem / 3, o = rem % 3;
    int c = 8*j + 2*tt;
    sW3P[tid] = pk2(W3[c*3 + o], W3[(c+1)*3 + o]);
  }
  __syncthreads();

  // ---- per-lane constant fragments (registers, loaded once from gmem) ----
  // B frag for mma m16n8k16 (col): b0=(k=2t,n),(k=2t+1,n); b1 same with k+8. n = 8j+g.
  u32 Bf[8][4][2];
  #pragma unroll
  for (int j = 0; j < 8; j++) {
    int n = 8*j + g;
    #pragma unroll
    for (int kk = 0; kk < 4; kk++) {
      int k0 = 16*kk + 2*t;
      Bf[j][kk][0] = bf16x2_of(__ldg(W2 + (k0    )*HID + n), __ldg(W2 + (k0 + 1)*HID + n));
      Bf[j][kk][1] = bf16x2_of(__ldg(W2 + (k0 + 8)*HID + n), __ldg(W2 + (k0 + 9)*HID + n));
    }
  }
  // b2 in D-fragment layout (cols 8j+2t, 8j+2t+1)
  float b2lo[8], b2hi[8];
  #pragma unroll
  for (int j = 0; j < 8; j++) {
    b2lo[j] = __ldg(b2 + 8*j + 2*t);
    b2hi[j] = __ldg(b2 + 8*j + 2*t + 1);
  }
  float b3r[3] = {__ldg(b3 + 0), __ldg(b3 + 1), __ldg(b3 + 2)};
  const float sc = __ldg(scale);

  const int row_ = blockIdx.x * TPB + tid;
  const int row  = (row_ < nrows) ? row_ : (nrows - 1);   // clamp; keep all lanes active

  // ---- prologue: s1[j] = b1[j] + sensory . W1[3:64, j]  (f32, to smem quads) ----
  {
    const float* srow = sens + (size_t)row * SENS;
    #pragma unroll
    for (int half = 0; half < 2; half++) {
      float4 acc[8];
      const float4* b1v = (const float4*)b1;
      #pragma unroll
      for (int q = 0; q < 8; q++) acc[q] = __ldg(b1v + half*8 + q);
      for (int s2 = 0; s2 < SENS; s2++) {
        float sv = __ldg(srow + s2);
        const float4* wr = (const float4*)(W1 + (3 + s2) * HID) + half*8;
        #pragma unroll
        for (int q = 0; q < 8; q++) {
          float4 w = __ldg(wr + q);
          acc[q].x = fmaf(sv, w.x, acc[q].x);
          acc[q].y = fmaf(sv, w.y, acc[q].y);
          acc[q].z = fmaf(sv, w.z, acc[q].z);
          acc[q].w = fmaf(sv, w.w, acc[q].w);
        }
      }
      #pragma unroll
      for (int q = 0; q < 8; q++) sS1q[(half*8 + q)*TPB + tid] = acc[q];
    }
  }

  // ---- integrate ----
  float y0 = __ldg(pad0 + (size_t)row*3 + 0);
  float y1 = __ldg(pad0 + (size_t)row*3 + 1);
  float y2 = __ldg(pad0 + (size_t)row*3 + 2);
  const float h = 1.0f / (float)NSTEPS;

  const u32 warpA = smem_base + OFF_A + wid * 4096;   // 32 rows x 128B
  float kst[6][3];

  #pragma unroll 1
  for (int st = 0; st < NSTEPS; st++) {
    float t0 = (float)st * h;

    #pragma unroll 1
    for (int s = 0; s < 6; s++) {
      float ys0 = y0, ys1 = y1, ys2 = y2;
      #pragma unroll
      for (int m = 0; m < 5; m++) {
        if (m < s) {
          float a = h * c_A[s][m];
          ys0 = fmaf(a, kst[m][0], ys0);
          ys1 = fmaf(a, kst[m][1], ys1);
          ys2 = fmaf(a, kst[m][2], ys2);
        }
      }
      float ts = fmaf(c_C[s], h, t0);

      // ---- layer 1 (scalar f32) -> bf16 A-tile row (swizzled chunks) ----
      #pragma unroll
      for (int jb = 0; jb < 8; jb++) {            // 8 units per 16B chunk
        float4 sA = sS1q[(jb*2 + 0)*TPB + tid];
        float4 sB = sS1q[(jb*2 + 1)*TPB + tid];
        float pre[8];
        pre[0]=sA.x; pre[1]=sA.y; pre[2]=sA.z; pre[3]=sA.w;
        pre[4]=sB.x; pre[5]=sB.y; pre[6]=sB.z; pre[7]=sB.w;
        u32 pkd[4];
        #pragma unroll
        for (int q = 0; q < 4; q++) {
          int j0 = jb*8 + q*2;
          float4 wA = ((const float4*)sW1y)[j0];
          float4 wB = ((const float4*)sW1y)[j0 + 1];
          float pa = fmaf(ys0, wA.x, pre[q*2]);
          float pb = fmaf(ys0, wB.x, pre[q*2 + 1]);
          pa = fmaf(ys1, wA.y, pa);  pb = fmaf(ys1, wB.y, pb);
          pa = fmaf(ys2, wA.z, pa);  pb = fmaf(ys2, wB.z, pb);
          pa = fmaf(ts,  wA.w, pa);  pb = fmaf(ts,  wB.w, pb);
          pkd[q] = bf16x2_of(ftanh(pa), ftanh(pb));
        }
        u32 ast = warpA + (u32)(lane*128 + ((jb ^ (lane & 7)) * 16));
        asm volatile("st.shared.v4.b32 [%0], {%1,%2,%3,%4};"
                     :: "r"(ast), "r"(pkd[0]), "r"(pkd[1]), "r"(pkd[2]), "r"(pkd[3]) : "memory");
      }
      __syncwarp();

      // ---- D[32,64] = h1 @ W2 via 64 mma.sync (acc init = b2) ----
      float d[2][8][4];
      #pragma unroll
      for (int m = 0; m < 2; m++)
        #pragma unroll
        for (int j = 0; j < 8; j++) {
          d[m][j][0] = b2lo[j]; d[m][j][1] = b2hi[j];
          d[m][j][2] = b2lo[j]; d[m][j][3] = b2hi[j];
        }

      #pragma unroll
      for (int kk = 0; kk < 4; kk++) {
        u32 a0[4], a1[4];
        int rsel = lane & 15;
        int gch  = kk*2 + (lane >> 4);
        u32 ad0 = warpA + (u32)(rsel*128 + ((gch ^ (rsel & 7)) * 16));
        int rsel1 = 16 + rsel;
        u32 ad1 = warpA + (u32)(rsel1*128 + ((gch ^ (rsel1 & 7)) * 16));
        ldmx4(a0[0], a0[1], a0[2], a0[3], ad0);
        ldmx4(a1[0], a1[1], a1[2], a1[3], ad1);
        #pragma unroll
        for (int j = 0; j < 8; j++) {
          mma16816(d[0][j][0], d[0][j][1], d[0][j][2], d[0][j][3],
                   a0[0], a0[1], a0[2], a0[3], Bf[j][kk][0], Bf[j][kk][1]);
          mma16816(d[1][j][0], d[1][j][1], d[1][j][2], d[1][j][3],
                   a1[0], a1[1], a1[2], a1[3], Bf[j][kk][0], Bf[j][kk][1]);
        }
      }
      __syncwarp();

      // ---- epilogue in fragment layout: tanh + packed layer-3 partials ----
      u64 oacc[4][3];
      #pragma unroll
      for (int sl = 0; sl < 4; sl++) { oacc[sl][0] = 0; oacc[sl][1] = 0; oacc[sl][2] = 0; }

      #pragma unroll
      for (int m = 0; m < 2; m++)
        #pragma unroll
        for (int j = 0; j < 8; j++) {
          float h00 = ftanh(d[m][j][0]);
          float h01 = ftanh(d[m][j][1]);
          float h10 = ftanh(d[m][j][2]);
          float h11 = ftanh(d[m][j][3]);
          u64 hp0 = pk2(h00, h01);
          u64 hp1 = pk2(h10, h11);
          const u64* wp = sW3P + (j*4 + t)*3;
          u64 w0 = wp[0], w1 = wp[1], w2v = wp[2];
          oacc[2*m + 0][0] = fma2(hp0, w0,  oacc[2*m + 0][0]);
          oacc[2*m + 1][0] = fma2(hp1, w0,  oacc[2*m + 1][0]);
          oacc[2*m + 0][1] = fma2(hp0, w1,  oacc[2*m + 0][1]);
          oacc[2*m + 1][1] = fma2(hp1, w1,  oacc[2*m + 1][1]);
          oacc[2*m + 0][2] = fma2(hp0, w2v, oacc[2*m + 0][2]);
          oacc[2*m + 1][2] = fma2(hp1, w2v, oacc[2*m + 1][2]);
        }

      // quad reduce (cols) then route to row owners
      float rs[4][3];
      #pragma unroll
      for (int sl = 0; sl < 4; sl++)
        #pragma unroll
        for (int o = 0; o < 3; o++) {
          float lo, hi; upk2(oacc[sl][o], lo, hi);
          float v = lo + hi;
          v += __shfl_xor_sync(0xffffffffu, v, 1);
          v += __shfl_xor_sync(0xffffffffu, v, 2);
          rs[sl][o] = v;
        }
      int srcl = (lane & 7) * 4;
      int slot = lane >> 3;
      #pragma unroll
      for (int o = 0; o < 3; o++) {
        float v0 = __shfl_sync(0xffffffffu, rs[0][o], srcl);
        float v1 = __shfl_sync(0xffffffffu, rs[1][o], srcl);
        float v2 = __shfl_sync(0xffffffffu, rs[2][o], srcl);
        float v3 = __shfl_sync(0xffffffffu, rs[3][o], srcl);
        float v = (slot == 0) ? v0 : (slot == 1) ? v1 : (slot == 2) ? v2 : v3;
        kst[s][o] = ftanh(v + b3r[o]) * sc;
      }
    }

    #pragma unroll
    for (int m = 0; m < 6; m++) {
      float bm = h * c_Bw[m];
      y0 = fmaf(bm, kst[m][0], y0);
      y1 = fmaf(bm, kst[m][1], y1);
      y2 = fmaf(bm, kst[m][2], y2);
    }
  }

  if (row_ < nrows) {
    out[(size_t)row*3 + 0] = y0;
    out[(size_t)row*3 + 1] = y1;
    out[(size_t)row*3 + 2] = y2;
  }
}

extern "C" void kernel_launch(void* const* d_in, const int* in_sizes, int n_in,
                              void* d_out, int out_size) {
  const float* pad0  = (const float*)d_in[0];
  const float* sens  = (const float*)d_in[1];
  const float* W1    = (const float*)d_in[2];
  const float* b1    = (const float*)d_in[3];
  const float* W2    = (const float*)d_in[4];
  const float* b2    = (const float*)d_in[5];
  const float* W3    = (const float*)d_in[6];
  const float* b3    = (const float*)d_in[7];
  const float* scale = (const float*)d_in[8];
  float* out = (float*)d_out;

  const int nrows = in_sizes[0] / 3;
  cudaFuncSetAttribute(ode_kernel, cudaFuncAttributeMaxDynamicSharedMemorySize, SMEM_BYTES);

  const int grid = (nrows + TPB - 1) / TPB;
  ode_kernel<<<grid, TPB, SMEM_BYTES>>>(pad0, sens, W1, b1, W2, b2, W3, b3, scale, out, nrows);
}

// round 9
// speedup vs baseline: 4.8172x; 1.0702x over previous
#include <cuda_runtime.h>
#include <cuda_bf16.h>

#define SENS 61
#define HID  64
#define NSTEPS 10
#define TPB  128

typedef unsigned long long u64;
typedef unsigned int u32;

// Dormand–Prince 5(4) tableau
__constant__ float c_A[6][5] = {
  {0.f, 0.f, 0.f, 0.f, 0.f},
  {(float)(1.0/5.0), 0.f, 0.f, 0.f, 0.f},
  {(float)(3.0/40.0), (float)(9.0/40.0), 0.f, 0.f, 0.f},
  {(float)(44.0/45.0), (float)(-56.0/15.0), (float)(32.0/9.0), 0.f, 0.f},
  {(float)(19372.0/6561.0), (float)(-25360.0/2187.0), (float)(64448.0/6561.0), (float)(-212.0/729.0), 0.f},
  {(float)(9017.0/3168.0), (float)(-355.0/33.0), (float)(46732.0/5247.0), (float)(49.0/176.0), (float)(-5103.0/18656.0)}
};
__constant__ float c_C[6] = {0.f, 0.2f, 0.3f, 0.8f, (float)(8.0/9.0), 1.f};
__constant__ float c_Bw[6] = {(float)(35.0/384.0), 0.f, (float)(500.0/1113.0),
                              (float)(125.0/192.0), (float)(-2187.0/6784.0), (float)(11.0/84.0)};

// ---- helpers ----
__device__ __forceinline__ float ftanh(float x) {
  float r; asm("tanh.approx.f32 %0, %1;" : "=f"(r) : "f"(x)); return r;
}
__device__ __forceinline__ u64 pk2(float lo, float hi) {
  u64 r; asm("mov.b64 %0, {%1, %2};" : "=l"(r) : "f"(lo), "f"(hi)); return r;
}
__device__ __forceinline__ void upk2(u64 v, float& lo, float& hi) {
  asm("mov.b64 {%0, %1}, %2;" : "=f"(lo), "=f"(hi) : "l"(v));
}
__device__ __forceinline__ u64 fma2(u64 a, u64 b, u64 c) {
  u64 d; asm("fma.rn.f32x2 %0, %1, %2, %3;" : "=l"(d) : "l"(a), "l"(b), "l"(c)); return d;
}
__device__ __forceinline__ u32 bf16x2_of(float lo, float hi) {
  u32 r; asm("cvt.rn.bf16x2.f32 %0, %1, %2;" : "=r"(r) : "f"(hi), "f"(lo)); return r; // upper=hi, lower=lo
}
__device__ __forceinline__ u32 smem_u32(const void* p) {
  u32 a; asm("{ .reg .u64 t; cvta.to.shared.u64 t, %1; cvt.u32.u64 %0, t; }" : "=r"(a) : "l"(p));
  return a;
}
__device__ __forceinline__ void ldmx4(u32& r0, u32& r1, u32& r2, u32& r3, u32 addr) {
  asm volatile("ldmatrix.sync.aligned.m8n8.x4.shared.b16 {%0,%1,%2,%3}, [%4];"
               : "=r"(r0), "=r"(r1), "=r"(r2), "=r"(r3) : "r"(addr));
}
__device__ __forceinline__ void mma16816(float& d0, float& d1, float& d2, float& d3,
                                         u32 a0, u32 a1, u32 a2, u32 a3, u32 b0, u32 b1) {
  asm volatile("mma.sync.aligned.m16n8k16.row.col.f32.bf16.bf16.f32 "
               "{%0,%1,%2,%3}, {%4,%5,%6,%7}, {%8,%9}, {%0,%1,%2,%3};"
               : "+f"(d0), "+f"(d1), "+f"(d2), "+f"(d3)
               : "r"(a0), "r"(a1), "r"(a2), "r"(a3), "r"(b0), "r"(b1));
}

// smem byte offsets
#define OFF_A    0                          // 4 warps * 32 rows * 128B = 16384 (A-tile, bf16, swizzled)
#define OFF_S1   16384                      // float4[16][TPB] = 32768 (per-thread sensory term)
#define OFF_W1Y  (OFF_S1 + 32768)           // float4[64] = 1024
#define OFF_BF   (OFF_W1Y + 1024)           // uint4[4 kk][4 jp][32 lane] = 8192 (W2 B-fragments)
#define OFF_B2F  (OFF_BF + 8192)            // float4[4 t][4 q] = 256 (b2 fragments)
#define OFF_W3A  (OFF_B2F + 256)            // ulonglong2[32] = 512 (W3 pairs o=0,1)
#define OFF_W3B  (OFF_W3A + 512)            // u64[32] = 256 (W3 pairs o=2)
#define SMEM_BYTES (OFF_W3B + 256)          // 59392

__global__ void __launch_bounds__(TPB, 3)
ode_kernel(const float* __restrict__ pad0, const float* __restrict__ sens,
           const float* __restrict__ W1, const float* __restrict__ b1,
           const float* __restrict__ W2, const float* __restrict__ b2,
           const float* __restrict__ W3, const float* __restrict__ b3,
           const float* __restrict__ scale, float* __restrict__ out, int nrows)
{
  extern __shared__ char smem[];
  const u32 smem_base = smem_u32(smem);
  const int tid  = threadIdx.x;
  const int lane = tid & 31;
  const int wid  = tid >> 5;
  const int t    = lane & 3;      // thread-in-group

  float* sW1y = (float*)(smem + OFF_W1Y);
  float4* sS1q = (float4*)(smem + OFF_S1);
  const float4* sB2Fq = (const float4*)(smem + OFF_B2F);

  // ---- cooperative weight staging ----
  for (int j = tid; j < HID; j += TPB) {
    sW1y[j*4 + 0] = W1[0*HID + j];
    sW1y[j*4 + 1] = W1[1*HID + j];
    sW1y[j*4 + 2] = W1[2*HID + j];
    sW1y[j*4 + 3] = W1[64*HID + j];   // time row
  }
  // W2 B-fragments, per-lane layout: one copy shared by all warps
  if (tid < 32) {
    int gl = tid >> 2, tl = tid & 3;
    #pragma unroll
    for (int kk = 0; kk < 4; kk++) {
      #pragma unroll
      for (int jp = 0; jp < 4; jp++) {
        u32 v[4];
        #pragma unroll
        for (int e = 0; e < 2; e++) {     // j = 2*jp + e
          int n = 8*(2*jp + e) + gl;
          int k0 = 16*kk + 2*tl;
          v[2*e + 0] = bf16x2_of(__ldg(W2 + (k0    )*HID + n), __ldg(W2 + (k0 + 1)*HID + n));
          v[2*e + 1] = bf16x2_of(__ldg(W2 + (k0 + 8)*HID + n), __ldg(W2 + (k0 + 9)*HID + n));
        }
        *(uint4*)(smem + OFF_BF + (((kk*4 + jp)*32) + tid)*16) = make_uint4(v[0], v[1], v[2], v[3]);
      }
    }
  }
  // b2 fragments: [t][q] = {b2[16q+2t], b2[16q+2t+1], b2[16q+8+2t], b2[16q+8+2t+1]}
  if (tid < 16) {
    int tt = tid >> 2, q = tid & 3;
    *(float4*)(smem + OFF_B2F + tid*16) =
      make_float4(__ldg(b2 + 16*q + 2*tt),     __ldg(b2 + 16*q + 2*tt + 1),
                  __ldg(b2 + 16*q + 8 + 2*tt), __ldg(b2 + 16*q + 8 + 2*tt + 1));
  }
  // W3 fragment pairs: index (j*4 + t), c = 8j + 2t
  if (tid < 32) {
    int j = tid >> 2, tt = tid & 3;
    int c = 8*j + 2*tt;
    ulonglong2 wab;
    wab.x = pk2(__ldg(W3 + c*3 + 0), __ldg(W3 + (c+1)*3 + 0));
    wab.y = pk2(__ldg(W3 + c*3 + 1), __ldg(W3 + (c+1)*3 + 1));
    *(ulonglong2*)(smem + OFF_W3A + tid*16) = wab;
    *(u64*)(smem + OFF_W3B + tid*8) = pk2(__ldg(W3 + c*3 + 2), __ldg(W3 + (c+1)*3 + 2));
  }
  __syncthreads();

  float b3r[3] = {__ldg(b3 + 0), __ldg(b3 + 1), __ldg(b3 + 2)};
  const float sc = __ldg(scale);

  const int row_ = blockIdx.x * TPB + tid;
  const int row  = (row_ < nrows) ? row_ : (nrows - 1);   // clamp; keep all lanes active

  // ---- prologue: s1[j] = b1[j] + sensory . W1[3:64, j]  (f32, to smem quads) ----
  {
    const float* srow = sens + (size_t)row * SENS;
    #pragma unroll
    for (int half = 0; half < 2; half++) {
      float4 acc[8];
      const float4* b1v = (const float4*)b1;
      #pragma unroll
      for (int q = 0; q < 8; q++) acc[q] = __ldg(b1v + half*8 + q);
      for (int s2 = 0; s2 < SENS; s2++) {
        float sv = __ldg(srow + s2);
        const float4* wr = (const float4*)(W1 + (3 + s2) * HID) + half*8;
        #pragma unroll
        for (int q = 0; q < 8; q++) {
          float4 w = __ldg(wr + q);
          acc[q].x = fmaf(sv, w.x, acc[q].x);
          acc[q].y = fmaf(sv, w.y, acc[q].y);
          acc[q].z = fmaf(sv, w.z, acc[q].z);
          acc[q].w = fmaf(sv, w.w, acc[q].w);
        }
      }
      #pragma unroll
      for (int q = 0; q < 8; q++) sS1q[(half*8 + q)*TPB + tid] = acc[q];
    }
  }

  // ---- integrate ----
  float y0 = __ldg(pad0 + (size_t)row*3 + 0);
  float y1 = __ldg(pad0 + (size_t)row*3 + 1);
  float y2 = __ldg(pad0 + (size_t)row*3 + 2);
  const float h = 1.0f / (float)NSTEPS;

  const u32 warpA = smem_base + OFF_A + wid * 4096;   // 32 rows x 128B
  float kst[6][3];

  #pragma unroll 1
  for (int st = 0; st < NSTEPS; st++) {
    float t0 = (float)st * h;

    #pragma unroll 1
    for (int s = 0; s < 6; s++) {
      float ys0 = y0, ys1 = y1, ys2 = y2;
      #pragma unroll
      for (int m = 0; m < 5; m++) {
        if (m < s) {
          float a = h * c_A[s][m];
          ys0 = fmaf(a, kst[m][0], ys0);
          ys1 = fmaf(a, kst[m][1], ys1);
          ys2 = fmaf(a, kst[m][2], ys2);
        }
      }
      float ts = fmaf(c_C[s], h, t0);

      // ---- layer 1 (scalar f32) -> bf16 A-tile row (swizzled chunks) ----
      #pragma unroll
      for (int jb = 0; jb < 8; jb++) {            // 8 units per 16B chunk
        float4 sA = sS1q[(jb*2 + 0)*TPB + tid];
        float4 sB = sS1q[(jb*2 + 1)*TPB + tid];
        float pre[8];
        pre[0]=sA.x; pre[1]=sA.y; pre[2]=sA.z; pre[3]=sA.w;
        pre[4]=sB.x; pre[5]=sB.y; pre[6]=sB.z; pre[7]=sB.w;
        u32 pkd[4];
        #pragma unroll
        for (int q = 0; q < 4; q++) {
          int j0 = jb*8 + q*2;
          float4 wA = ((const float4*)sW1y)[j0];
          float4 wB = ((const float4*)sW1y)[j0 + 1];
          float pa = fmaf(ys0, wA.x, pre[q*2]);
          float pb = fmaf(ys0, wB.x, pre[q*2 + 1]);
          pa = fmaf(ys1, wA.y, pa);  pb = fmaf(ys1, wB.y, pb);
          pa = fmaf(ys2, wA.z, pa);  pb = fmaf(ys2, wB.z, pb);
          pa = fmaf(ts,  wA.w, pa);  pb = fmaf(ts,  wB.w, pb);
          pkd[q] = bf16x2_of(ftanh(pa), ftanh(pb));
        }
        u32 ast = warpA + (u32)(lane*128 + ((jb ^ (lane & 7)) * 16));
        asm volatile("st.shared.v4.b32 [%0], {%1,%2,%3,%4};"
                     :: "r"(ast), "r"(pkd[0]), "r"(pkd[1]), "r"(pkd[2]), "r"(pkd[3]) : "memory");
      }
      __syncwarp();

      // ---- D[32,64] = h1 @ W2 via 64 mma.sync (acc init = b2 from smem) ----
      float d[2][8][4];
      {
        float4 bq[4];
        #pragma unroll
        for (int q = 0; q < 4; q++) bq[q] = sB2Fq[t*4 + q];
        #pragma unroll
        for (int m = 0; m < 2; m++)
          #pragma unroll
          for (int j = 0; j < 8; j++) {
            float lo = (j & 1) ? bq[j>>1].z : bq[j>>1].x;
            float hi = (j & 1) ? bq[j>>1].w : bq[j>>1].y;
            d[m][j][0] = lo; d[m][j][1] = hi;
            d[m][j][2] = lo; d[m][j][3] = hi;
          }
      }

      #pragma unroll
      for (int kk = 0; kk < 4; kk++) {
        u32 a0[4], a1[4];
        int rsel = lane & 15;
        int gch  = kk*2 + (lane >> 4);
        u32 ad0 = warpA + (u32)(rsel*128 + ((gch ^ (rsel & 7)) * 16));
        int rsel1 = 16 + rsel;
        u32 ad1 = warpA + (u32)(rsel1*128 + ((gch ^ (rsel1 & 7)) * 16));
        ldmx4(a0[0], a0[1], a0[2], a0[3], ad0);
        ldmx4(a1[0], a1[1], a1[2], a1[3], ad1);
        #pragma unroll
        for (int jp = 0; jp < 4; jp++) {
          uint4 Bq = *(const uint4*)(smem + OFF_BF + (((kk*4 + jp)*32) + lane)*16);
          mma16816(d[0][2*jp][0], d[0][2*jp][1], d[0][2*jp][2], d[0][2*jp][3],
                   a0[0], a0[1], a0[2], a0[3], Bq.x, Bq.y);
          mma16816(d[1][2*jp][0], d[1][2*jp][1], d[1][2*jp][2], d[1][2*jp][3],
                   a1[0], a1[1], a1[2], a1[3], Bq.x, Bq.y);
          mma16816(d[0][2*jp+1][0], d[0][2*jp+1][1], d[0][2*jp+1][2], d[0][2*jp+1][3],
                   a0[0], a0[1], a0[2], a0[3], Bq.z, Bq.w);
          mma16816(d[1][2*jp+1][0], d[1][2*jp+1][1], d[1][2*jp+1][2], d[1][2*jp+1][3],
                   a1[0], a1[1], a1[2], a1[3], Bq.z, Bq.w);
        }
      }
      __syncwarp();

      // ---- epilogue in fragment layout: tanh + packed layer-3 partials ----
      u64 oacc[4][3];
      #pragma unroll
      for (int sl = 0; sl < 4; sl++) { oacc[sl][0] = 0; oacc[sl][1] = 0; oacc[sl][2] = 0; }

      #pragma unroll
      for (int m = 0; m < 2; m++)
        #pragma unroll
        for (int j = 0; j < 8; j++) {
          float h00 = ftanh(d[m][j][0]);
          float h01 = ftanh(d[m][j][1]);
          float h10 = ftanh(d[m][j][2]);
          float h11 = ftanh(d[m][j][3]);
          u64 hp0 = pk2(h00, h01);
          u64 hp1 = pk2(h10, h11);
          ulonglong2 wab = *(const ulonglong2*)(smem + OFF_W3A + (j*4 + t)*16);
          u64 w2v = *(const u64*)(smem + OFF_W3B + (j*4 + t)*8);
          oacc[2*m + 0][0] = fma2(hp0, wab.x, oacc[2*m + 0][0]);
          oacc[2*m + 1][0] = fma2(hp1, wab.x, oacc[2*m + 1][0]);
          oacc[2*m + 0][1] = fma2(hp0, wab.y, oacc[2*m + 0][1]);
          oacc[2*m + 1][1] = fma2(hp1, wab.y, oacc[2*m + 1][1]);
          oacc[2*m + 0][2] = fma2(hp0, w2v,  oacc[2*m + 0][2]);
          oacc[2*m + 1][2] = fma2(hp1, w2v,  oacc[2*m + 1][2]);
        }

      // quad reduce (cols) then route to row owners
      float rs[4][3];
      #pragma unroll
      for (int sl = 0; sl < 4; sl++)
        #pragma unroll
        for (int o = 0; o < 3; o++) {
          float lo, hi; upk2(oacc[sl][o], lo, hi);
          float v = lo + hi;
          v += __shfl_xor_sync(0xffffffffu, v, 1);
          v += __shfl_xor_sync(0xffffffffu, v, 2);
          rs[sl][o] = v;
        }
      int srcl = (lane & 7) * 4;
      int slot = lane >> 3;
      #pragma unroll
      for (int o = 0; o < 3; o++) {
        float v0 = __shfl_sync(0xffffffffu, rs[0][o], srcl);
        float v1 = __shfl_sync(0xffffffffu, rs[1][o], srcl);
        float v2 = __shfl_sync(0xffffffffu, rs[2][o], srcl);
        float v3 = __shfl_sync(0xffffffffu, rs[3][o], srcl);
        float v = (slot == 0) ? v0 : (slot == 1) ? v1 : (slot == 2) ? v2 : v3;
        kst[s][o] = ftanh(v + b3r[o]) * sc;
      }
    }

    #pragma unroll
    for (int m = 0; m < 6; m++) {
      float bm = h * c_Bw[m];
      y0 = fmaf(bm, kst[m][0], y0);
      y1 = fmaf(bm, kst[m][1], y1);
      y2 = fmaf(bm, kst[m][2], y2);
    }
  }

  if (row_ < nrows) {
    out[(size_t)row*3 + 0] = y0;
    out[(size_t)row*3 + 1] = y1;
    out[(size_t)row*3 + 2] = y2;
  }
}

extern "C" void kernel_launch(void* const* d_in, const int* in_sizes, int n_in,
                              void* d_out, int out_size) {
  const float* pad0  = (const float*)d_in[0];
  const float* sens  = (const float*)d_in[1];
  const float* W1    = (const float*)d_in[2];
  const float* b1    = (const float*)d_in[3];
  const float* W2    = (const float*)d_in[4];
  const float* b2    = (const float*)d_in[5];
  const float* W3    = (const float*)d_in[6];
  const float* b3    = (const float*)d_in[7];
  const float* scale = (const float*)d_in[8];
  float* out = (float*)d_out;

  const int nrows = in_sizes[0] / 3;
  cudaFuncSetAttribute(ode_kernel, cudaFuncAttributeMaxDynamicSharedMemorySize, SMEM_BYTES);

  const int grid = (nrows + TPB - 1) / TPB;
  ode_kernel<<<grid, TPB, SMEM_BYTES>>>(pad0, sens, W1, b1, W2, b2, W3, b3, scale, out, nrows);
}

// round 10
// speedup vs baseline: 5.4308x; 1.1274x over previous
#include <cuda_runtime.h>
#include <cuda_bf16.h>

#define SENS 61
#define HID  64
#define NSTEPS 10
#define TPB  128

typedef unsigned long long u64;
typedef unsigned int u32;

// Dormand–Prince 5(4) tableau
__constant__ float c_A[6][5] = {
  {0.f, 0.f, 0.f, 0.f, 0.f},
  {(float)(1.0/5.0), 0.f, 0.f, 0.f, 0.f},
  {(float)(3.0/40.0), (float)(9.0/40.0), 0.f, 0.f, 0.f},
  {(float)(44.0/45.0), (float)(-56.0/15.0), (float)(32.0/9.0), 0.f, 0.f},
  {(float)(19372.0/6561.0), (float)(-25360.0/2187.0), (float)(64448.0/6561.0), (float)(-212.0/729.0), 0.f},
  {(float)(9017.0/3168.0), (float)(-355.0/33.0), (float)(46732.0/5247.0), (float)(49.0/176.0), (float)(-5103.0/18656.0)}
};
__constant__ float c_C[6] = {0.f, 0.2f, 0.3f, 0.8f, (float)(8.0/9.0), 1.f};
__constant__ float c_Bw[6] = {(float)(35.0/384.0), 0.f, (float)(500.0/1113.0),
                              (float)(125.0/192.0), (float)(-2187.0/6784.0), (float)(11.0/84.0)};

// ---- helpers ----
__device__ __forceinline__ float ftanh(float x) {
  float r; asm("tanh.approx.f32 %0, %1;" : "=f"(r) : "f"(x)); return r;
}
__device__ __forceinline__ u32 f16x2_of(float lo, float hi) {
  u32 r; asm("cvt.rn.f16x2.f32 %0, %1, %2;" : "=r"(r) : "f"(hi), "f"(lo)); return r; // upper=hi, lower=lo
}
__device__ __forceinline__ u32 tanh2(u32 x) {
  u32 r; asm("tanh.approx.f16x2 %0, %1;" : "=r"(r) : "r"(x)); return r;
}
__device__ __forceinline__ u32 smem_u32(const void* p) {
  u32 a; asm("{ .reg .u64 t; cvta.to.shared.u64 t, %1; cvt.u32.u64 %0, t; }" : "=r"(a) : "l"(p));
  return a;
}
__device__ __forceinline__ void ldmx4(u32& r0, u32& r1, u32& r2, u32& r3, u32 addr) {
  asm volatile("ldmatrix.sync.aligned.m8n8.x4.shared.b16 {%0,%1,%2,%3}, [%4];"
               : "=r"(r0), "=r"(r1), "=r"(r2), "=r"(r3) : "r"(addr));
}
__device__ __forceinline__ void mmaf16(float& d0, float& d1, float& d2, float& d3,
                                       u32 a0, u32 a1, u32 a2, u32 a3, u32 b0, u32 b1) {
  asm volatile("mma.sync.aligned.m16n8k16.row.col.f32.f16.f16.f32 "
               "{%0,%1,%2,%3}, {%4,%5,%6,%7}, {%8,%9}, {%0,%1,%2,%3};"
               : "+f"(d0), "+f"(d1), "+f"(d2), "+f"(d3)
               : "r"(a0), "r"(a1), "r"(a2), "r"(a3), "r"(b0), "r"(b1));
}

// smem byte offsets
#define OFF_A    0                          // 4 warps * 32 rows * 128B = 16384 (A-tile f16 / result staging)
#define OFF_S1   16384                      // float4[16][TPB] = 32768 (per-thread sensory term)
#define OFF_W1Y  (OFF_S1 + 32768)           // float4[64] = 1024
#define OFF_BF   (OFF_W1Y + 1024)           // uint4[4 kk][4 jp][32 lane] = 8192 (W2 B-fragments, f16)
#define OFF_B2F  (OFF_BF + 8192)            // float4[4 t][4 q] = 256 (b2 fragments)
#define OFF_W3F  (OFF_B2F + 256)            // uint2[4 kk2][32 lane] = 1024 (W3 B-fragments, f16, N-pad 8)
#define SMEM_BYTES (OFF_W3F + 1024)         // 59648

__global__ void __launch_bounds__(TPB, 3)
ode_kernel(const float* __restrict__ pad0, const float* __restrict__ sens,
           const float* __restrict__ W1, const float* __restrict__ b1,
           const float* __restrict__ W2, const float* __restrict__ b2,
           const float* __restrict__ W3, const float* __restrict__ b3,
           const float* __restrict__ scale, float* __restrict__ out, int nrows)
{
  extern __shared__ char smem[];
  const u32 smem_base = smem_u32(smem);
  const int tid  = threadIdx.x;
  const int lane = tid & 31;
  const int wid  = tid >> 5;
  const int g    = lane >> 2;     // fragment group id (row within 8)
  const int t    = lane & 3;      // thread-in-group (col pair)

  float* sW1y = (float*)(smem + OFF_W1Y);
  float4* sS1q = (float4*)(smem + OFF_S1);
  const float4* sB2Fq = (const float4*)(smem + OFF_B2F);

  // ---- cooperative weight staging ----
  for (int j = tid; j < HID; j += TPB) {
    sW1y[j*4 + 0] = W1[0*HID + j];
    sW1y[j*4 + 1] = W1[1*HID + j];
    sW1y[j*4 + 2] = W1[2*HID + j];
    sW1y[j*4 + 3] = W1[64*HID + j];   // time row
  }
  // W2 B-fragments (f16), per-lane layout, one copy for all warps
  if (tid < 32) {
    int gl = tid >> 2, tl = tid & 3;
    #pragma unroll
    for (int kk = 0; kk < 4; kk++) {
      #pragma unroll
      for (int jp = 0; jp < 4; jp++) {
        u32 v[4];
        #pragma unroll
        for (int e = 0; e < 2; e++) {     // j = 2*jp + e
          int n = 8*(2*jp + e) + gl;
          int k0 = 16*kk + 2*tl;
          v[2*e + 0] = f16x2_of(__ldg(W2 + (k0    )*HID + n), __ldg(W2 + (k0 + 1)*HID + n));
          v[2*e + 1] = f16x2_of(__ldg(W2 + (k0 + 8)*HID + n), __ldg(W2 + (k0 + 9)*HID + n));
        }
        *(uint4*)(smem + OFF_BF + (((kk*4 + jp)*32) + tid)*16) = make_uint4(v[0], v[1], v[2], v[3]);
      }
    }
  }
  // b2 fragments: [t][q] = {b2[16q+2t], b2[16q+2t+1], b2[16q+8+2t], b2[16q+8+2t+1]}
  if (tid < 16) {
    int tt = tid >> 2, q = tid & 3;
    *(float4*)(smem + OFF_B2F + tid*16) =
      make_float4(__ldg(b2 + 16*q + 2*tt),     __ldg(b2 + 16*q + 2*tt + 1),
                  __ldg(b2 + 16*q + 8 + 2*tt), __ldg(b2 + 16*q + 8 + 2*tt + 1));
  }
  // W3 B-fragments (f16): 4 k-blocks of 16; B tile 16(k) x 8(n), n>=3 zero-padded
  if (tid < 32) {
    int gl = tid >> 2, tl = tid & 3;
    #pragma unroll
    for (int kk2 = 0; kk2 < 4; kk2++) {
      int k0 = kk2*16 + 2*tl;
      float w0a = (gl < 3) ? __ldg(W3 + (k0    )*3 + gl) : 0.0f;
      float w0b = (gl < 3) ? __ldg(W3 + (k0 + 1)*3 + gl) : 0.0f;
      float w1a = (gl < 3) ? __ldg(W3 + (k0 + 8)*3 + gl) : 0.0f;
      float w1b = (gl < 3) ? __ldg(W3 + (k0 + 9)*3 + gl) : 0.0f;
      uint2 bw;
      bw.x = f16x2_of(w0a, w0b);
      bw.y = f16x2_of(w1a, w1b);
      *(uint2*)(smem + OFF_W3F + (kk2*32 + tid)*8) = bw;
    }
  }
  __syncthreads();

  float b3r[3] = {__ldg(b3 + 0), __ldg(b3 + 1), __ldg(b3 + 2)};
  const float sc = __ldg(scale);

  const int row_ = blockIdx.x * TPB + tid;
  const int row  = (row_ < nrows) ? row_ : (nrows - 1);   // clamp; keep all lanes active

  // ---- prologue: s1[j] = b1[j] + sensory . W1[3:64, j]  (f32, to smem quads) ----
  {
    const float* srow = sens + (size_t)row * SENS;
    #pragma unroll
    for (int half = 0; half < 2; half++) {
      float4 acc[8];
      const float4* b1v = (const float4*)b1;
      #pragma unroll
      for (int q = 0; q < 8; q++) acc[q] = __ldg(b1v + half*8 + q);
      for (int s2 = 0; s2 < SENS; s2++) {
        float sv = __ldg(srow + s2);
        const float4* wr = (const float4*)(W1 + (3 + s2) * HID) + half*8;
        #pragma unroll
        for (int q = 0; q < 8; q++) {
          float4 w = __ldg(wr + q);
          acc[q].x = fmaf(sv, w.x, acc[q].x);
          acc[q].y = fmaf(sv, w.y, acc[q].y);
          acc[q].z = fmaf(sv, w.z, acc[q].z);
          acc[q].w = fmaf(sv, w.w, acc[q].w);
        }
      }
      #pragma unroll
      for (int q = 0; q < 8; q++) sS1q[(half*8 + q)*TPB + tid] = acc[q];
    }
  }

  // ---- integrate ----
  float y0 = __ldg(pad0 + (size_t)row*3 + 0);
  float y1 = __ldg(pad0 + (size_t)row*3 + 1);
  float y2 = __ldg(pad0 + (size_t)row*3 + 2);
  const float h = 1.0f / (float)NSTEPS;

  const u32 warpA = smem_base + OFF_A + wid * 4096;   // 32 rows x 128B (A-tile, then result staging)
  float kst[6][3];

  #pragma unroll 1
  for (int st = 0; st < NSTEPS; st++) {
    float t0 = (float)st * h;

    #pragma unroll 1
    for (int s = 0; s < 6; s++) {
      float ys0 = y0, ys1 = y1, ys2 = y2;
      #pragma unroll
      for (int m = 0; m < 5; m++) {
        if (m < s) {
          float a = h * c_A[s][m];
          ys0 = fmaf(a, kst[m][0], ys0);
          ys1 = fmaf(a, kst[m][1], ys1);
          ys2 = fmaf(a, kst[m][2], ys2);
        }
      }
      float ts = fmaf(c_C[s], h, t0);

      // ---- layer 1 (scalar f32) -> f16x2 tanh -> f16 A-tile row (swizzled) ----
      #pragma unroll
      for (int jb = 0; jb < 8; jb++) {            // 8 units per 16B chunk
        float4 sA = sS1q[(jb*2 + 0)*TPB + tid];
        float4 sB = sS1q[(jb*2 + 1)*TPB + tid];
        float pre[8];
        pre[0]=sA.x; pre[1]=sA.y; pre[2]=sA.z; pre[3]=sA.w;
        pre[4]=sB.x; pre[5]=sB.y; pre[6]=sB.z; pre[7]=sB.w;
        u32 pkd[4];
        #pragma unroll
        for (int q = 0; q < 4; q++) {
          int j0 = jb*8 + q*2;
          float4 wA = ((const float4*)sW1y)[j0];
          float4 wB = ((const float4*)sW1y)[j0 + 1];
          float pa = fmaf(ys0, wA.x, pre[q*2]);
          float pb = fmaf(ys0, wB.x, pre[q*2 + 1]);
          pa = fmaf(ys1, wA.y, pa);  pb = fmaf(ys1, wB.y, pb);
          pa = fmaf(ys2, wA.z, pa);  pb = fmaf(ys2, wB.z, pb);
          pa = fmaf(ts,  wA.w, pa);  pb = fmaf(ts,  wB.w, pb);
          pkd[q] = tanh2(f16x2_of(pa, pb));       // 1 MUFU per 2 units
        }
        u32 ast = warpA + (u32)(lane*128 + ((jb ^ (lane & 7)) * 16));
        asm volatile("st.shared.v4.b32 [%0], {%1,%2,%3,%4};"
                     :: "r"(ast), "r"(pkd[0]), "r"(pkd[1]), "r"(pkd[2]), "r"(pkd[3]) : "memory");
      }
      __syncwarp();

      // ---- D[32,64] = h1 @ W2 via 32 mma.sync f16 (acc init = b2 from smem) ----
      float d[2][8][4];
      {
        float4 bq[4];
        #pragma unroll
        for (int q = 0; q < 4; q++) bq[q] = sB2Fq[t*4 + q];
        #pragma unroll
        for (int m = 0; m < 2; m++)
          #pragma unroll
          for (int j = 0; j < 8; j++) {
            float lo = (j & 1) ? bq[j>>1].z : bq[j>>1].x;
            float hi = (j & 1) ? bq[j>>1].w : bq[j>>1].y;
            d[m][j][0] = lo; d[m][j][1] = hi;
            d[m][j][2] = lo; d[m][j][3] = hi;
          }
      }

      #pragma unroll
      for (int kk = 0; kk < 4; kk++) {
        u32 a0[4], a1[4];
        int rsel = lane & 15;
        int gch  = kk*2 + (lane >> 4);
        u32 ad0 = warpA + (u32)(rsel*128 + ((gch ^ (rsel & 7)) * 16));
        int rsel1 = 16 + rsel;
        u32 ad1 = warpA + (u32)(rsel1*128 + ((gch ^ (rsel1 & 7)) * 16));
        ldmx4(a0[0], a0[1], a0[2], a0[3], ad0);
        ldmx4(a1[0], a1[1], a1[2], a1[3], ad1);
        #pragma unroll
        for (int jp = 0; jp < 4; jp++) {
          uint4 Bq = *(const uint4*)(smem + OFF_BF + (((kk*4 + jp)*32) + lane)*16);
          mmaf16(d[0][2*jp][0], d[0][2*jp][1], d[0][2*jp][2], d[0][2*jp][3],
                 a0[0], a0[1], a0[2], a0[3], Bq.x, Bq.y);
          mmaf16(d[1][2*jp][0], d[1][2*jp][1], d[1][2*jp][2], d[1][2*jp][3],
                 a1[0], a1[1], a1[2], a1[3], Bq.x, Bq.y);
          mmaf16(d[0][2*jp+1][0], d[0][2*jp+1][1], d[0][2*jp+1][2], d[0][2*jp+1][3],
                 a0[0], a0[1], a0[2], a0[3], Bq.z, Bq.w);
          mmaf16(d[1][2*jp+1][0], d[1][2*jp+1][1], d[1][2*jp+1][2], d[1][2*jp+1][3],
                 a1[0], a1[1], a1[2], a1[3], Bq.z, Bq.w);
        }
      }
      __syncwarp();

      // ---- epilogue: tanh2(D) feeds layer-3 MMA directly (D-frag == A-frag layout) ----
      float d2[2][4];
      #pragma unroll
      for (int m = 0; m < 2; m++) { d2[m][0]=0.f; d2[m][1]=0.f; d2[m][2]=0.f; d2[m][3]=0.f; }

      #pragma unroll
      for (int m = 0; m < 2; m++) {
        #pragma unroll
        for (int kk2 = 0; kk2 < 4; kk2++) {
          int j0 = 2*kk2;
          u32 a0v = tanh2(f16x2_of(d[m][j0  ][0], d[m][j0  ][1]));
          u32 a1v = tanh2(f16x2_of(d[m][j0  ][2], d[m][j0  ][3]));
          u32 a2v = tanh2(f16x2_of(d[m][j0+1][0], d[m][j0+1][1]));
          u32 a3v = tanh2(f16x2_of(d[m][j0+1][2], d[m][j0+1][3]));
          uint2 bw = *(const uint2*)(smem + OFF_W3F + (kk2*32 + lane)*8);
          mmaf16(d2[m][0], d2[m][1], d2[m][2], d2[m][3],
                 a0v, a1v, a2v, a3v, bw.x, bw.y);
        }
      }

      // ---- route D2 (cols 0..2) to row owners via per-warp smem staging (reuse A-tile) ----
      if (t == 0) {           // holds cols 0,1
        #pragma unroll
        for (int m = 0; m < 2; m++) {
          asm volatile("st.shared.v2.f32 [%0], {%1,%2};"
                       :: "r"(warpA + (u32)((16*m + g)*16)), "f"(d2[m][0]), "f"(d2[m][1]) : "memory");
          asm volatile("st.shared.v2.f32 [%0], {%1,%2};"
                       :: "r"(warpA + (u32)((16*m + g + 8)*16)), "f"(d2[m][2]), "f"(d2[m][3]) : "memory");
        }
      } else if (t == 1) {    // holds col 2 (in slot 0 of its pair)
        #pragma unroll
        for (int m = 0; m < 2; m++) {
          asm volatile("st.shared.f32 [%0], %1;"
                       :: "r"(warpA + (u32)((16*m + g)*16 + 8)), "f"(d2[m][0]) : "memory");
          asm volatile("st.shared.f32 [%0], %1;"
                       :: "r"(warpA + (u32)((16*m + g + 8)*16 + 8)), "f"(d2[m][2]) : "memory");
        }
      }
      __syncwarp();
      float v0, v1, v2w, v3w;
      asm volatile("ld.shared.v4.f32 {%0,%1,%2,%3}, [%4];"
                   : "=f"(v0), "=f"(v1), "=f"(v2w), "=f"(v3w)
                   : "r"(warpA + (u32)(lane*16)));
      kst[s][0] = ftanh(v0  + b3r[0]) * sc;
      kst[s][1] = ftanh(v1  + b3r[1]) * sc;
      kst[s][2] = ftanh(v2w + b3r[2]) * sc;
      __syncwarp();           // staging fully read before next eval overwrites A-tile
    }

    #pragma unroll
    for (int m = 0; m < 6; m++) {
      float bm = h * c_Bw[m];
      y0 = fmaf(bm, kst[m][0], y0);
      y1 = fmaf(bm, kst[m][1], y1);
      y2 = fmaf(bm, kst[m][2], y2);
    }
  }

  if (row_ < nrows) {
    out[(size_t)row*3 + 0] = y0;
    out[(size_t)row*3 + 1] = y1;
    out[(size_t)row*3 + 2] = y2;
  }
}

extern "C" void kernel_launch(void* const* d_in, const int* in_sizes, int n_in,
                              void* d_out, int out_size) {
  const float* pad0  = (const float*)d_in[0];
  const float* sens  = (const float*)d_in[1];
  const float* W1    = (const float*)d_in[2];
  const float* b1    = (const float*)d_in[3];
  const float* W2    = (const float*)d_in[4];
  const float* b2    = (const float*)d_in[5];
  const float* W3    = (const float*)d_in[6];
  const float* b3    = (const float*)d_in[7];
  const float* scale = (const float*)d_in[8];
  float* out = (float*)d_out;

  const int nrows = in_sizes[0] / 3;
  cudaFuncSetAttribute(ode_kernel, cudaFuncAttributeMaxDynamicSharedMemorySize, SMEM_BYTES);

  const int grid = (nrows + TPB - 1) / TPB;
  ode_kernel<<<grid, TPB, SMEM_BYTES>>>(pad0, sens, W1, b1, W2, b2, W3, b3, scale, out, nrows);
}